// round 2
// baseline (speedup 1.0000x reference)
#include <cuda_runtime.h>
#include <cstddef>

typedef unsigned long long u64;

// Problem shape (fixed by the dataset)
#define BB   8
#define CC   256
#define LL   2048
#define KK   8192
#define NQ   (BB*LL)          // 16384 queries
#define NEMB (BB*CC*LL)       // 4194304 emb elements

// GEMM tiling
#define TM      64            // queries per block tile
#define TN      128           // codes per block tile
#define KCH     32            // C-chunk staged in smem
#define NKT     (CC/KCH)      // 8 k-chunks
#define CBS_LD  (TN + 4)      // padded stride: kills 8-way STS conflicts
#define NSPLIT  4             // codebook split across blockIdx.y (tail balance)
#define KSPL    (KK/NSPLIT)   // 2048 codes per split
#define NTHREADS 256

// Packed fp32x2 FMA (Blackwell): 2 IEEE-exact fp32 FMAs per lane per instr.
#define FMA_F32X2(d, a, b, c) \
    asm("fma.rn.f32x2 %0, %1, %2, %3;" : "=l"(d) : "l"(a), "l"(b), "l"(c))
#define PACK_DUP(d, x) \
    asm("mov.b64 %0, {%1, %1};" : "=l"(d) : "r"(__float_as_uint(x)))
#define UNPACK2(lo, hi, v) \
    asm("mov.b64 {%0, %1}, %2;" : "=r"(lo), "=r"(hi) : "l"(v))

// Scratch (static device arrays; no allocation anywhere)
__device__ float g_csq[KK];
__device__ float g_pmax[NSPLIT][NQ];
__device__ int   g_pidx[NSPLIT][NQ];
__device__ float g_losspart[NQ/8];   // 2048 partials

// ---------------------------------------------------------------------------
// Kernel 0: per-code squared norms  (warp per codebook row)
// ---------------------------------------------------------------------------
__global__ void csq_kernel(const float* __restrict__ cb) {
    int w = threadIdx.x >> 5, lane = threadIdx.x & 31;
    int row = blockIdx.x * 8 + w;
    const float* r = cb + (size_t)row * CC;
    float s = 0.f;
#pragma unroll
    for (int j = 0; j < 8; j++) {
        float v = r[lane + j * 32];
        s = fmaf(v, v, s);
    }
#pragma unroll
    for (int off = 16; off; off >>= 1)
        s += __shfl_xor_sync(0xffffffffu, s, off);
    if (lane == 0) g_csq[row] = s;
}

// ---------------------------------------------------------------------------
// Kernel 1: fused dot GEMM (f32x2 packed) + running argmax of (csq - 2*dot)
//   grid: (NQ/TM, NSPLIT), block: 256 threads, dynamic smem
// ---------------------------------------------------------------------------
__global__ void __launch_bounds__(NTHREADS, 2)
dist_kernel(const float* __restrict__ x, const float* __restrict__ cb) {
    extern __shared__ float sm[];
    float* xs   = sm;                         // [CC][TM]      64 KB, resident
    float* cbs0 = xs + CC * TM;               // [KCH][CBS_LD] buffer 0
    float* cbs1 = cbs0 + KCH * CBS_LD;        // [KCH][CBS_LD] buffer 1
    float* rval = cbs1 + KCH * CBS_LD;        // [TM][16]
    int*   ridx = (int*)(rval + TM * 16);     // [TM][16]

    const int tid = threadIdx.x;
    const int bx  = blockIdx.x;
    const int split = blockIdx.y;
    const int b  = bx >> 5;                   // 32 m-tiles per batch (2048/64)
    const int l0 = (bx & 31) * TM;
    const float* xbase = x + (size_t)b * CC * LL + l0;

    // Stage the x tile once: xs[c][m] (coalesced: m contiguous in gmem)
    for (int i = tid; i < CC * (TM / 4); i += NTHREADS) {
        int c  = i >> 4;            // / (TM/4)
        int m4 = i & 15;
        float4 v = *(const float4*)(xbase + (size_t)c * LL + m4 * 4);
        *(float4*)(xs + c * TM + m4 * 4) = v;
    }

    const int tx = tid & 15;        // 16 -> n
    const int ty = tid >> 4;        // 16 -> m
    // Prefetch index decomposition (4 float4 per thread per chunk)
    int pf_np[4], pf_c4[4];
#pragma unroll
    for (int j = 0; j < 4; j++) {
        int i = tid + j * NTHREADS;
        pf_np[j] = i >> 3;
        pf_c4[j] = i & 7;
    }

    float bestv[4]; int besti[4];
#pragma unroll
    for (int i = 0; i < 4; i++) { bestv[i] = -3.0e38f; besti[i] = 0x7fffffff; }

    const int n_origin = split * KSPL;

    for (int nt = 0; nt < KSPL / TN; nt++) {
        const int n0 = n_origin + nt * TN;
        // acc2[im][jn]: packed pair of n = tx*8 + jn*2 + {0,1}
        u64 acc2[4][4];
#pragma unroll
        for (int im = 0; im < 4; im++)
#pragma unroll
            for (int jn = 0; jn < 4; jn++) acc2[im][jn] = 0ull;

        float4 pv[4];
        // Prologue: fetch + commit chunk 0
#pragma unroll
        for (int j = 0; j < 4; j++)
            pv[j] = *(const float4*)(cb + (size_t)(n0 + pf_np[j]) * CC + pf_c4[j] * 4);
#pragma unroll
        for (int j = 0; j < 4; j++) {
            float* d = cbs0 + pf_c4[j] * 4 * CBS_LD + pf_np[j];
            d[0] = pv[j].x; d[CBS_LD] = pv[j].y;
            d[2 * CBS_LD] = pv[j].z; d[3 * CBS_LD] = pv[j].w;
        }
        __syncthreads();   // also covers xs staging on nt==0

#pragma unroll 1
        for (int kt = 0; kt < NKT; kt++) {
            // Issue gmem fetch for next chunk (latency overlapped with compute)
            if (kt < NKT - 1) {
#pragma unroll
                for (int j = 0; j < 4; j++)
                    pv[j] = *(const float4*)(cb + (size_t)(n0 + pf_np[j]) * CC
                                             + (kt + 1) * KCH + pf_c4[j] * 4);
            }
            const float* xcol = xs + kt * KCH * TM + ty * 4;
            const float* bcol = (kt & 1 ? cbs1 : cbs0) + tx * 8;
#pragma unroll
            for (int cc = 0; cc < KCH; cc++) {
                float4 a = *(const float4*)(xcol + cc * TM);
                const float* bp = bcol + cc * CBS_LD;
                ulonglong2 q0 = *(const ulonglong2*)(bp);
                ulonglong2 q1 = *(const ulonglong2*)(bp + 4);
                u64 bv[4] = {q0.x, q0.y, q1.x, q1.y};
                u64 ad[4];
                PACK_DUP(ad[0], a.x); PACK_DUP(ad[1], a.y);
                PACK_DUP(ad[2], a.z); PACK_DUP(ad[3], a.w);
#pragma unroll
                for (int im = 0; im < 4; im++)
#pragma unroll
                    for (int jn = 0; jn < 4; jn++)
                        FMA_F32X2(acc2[im][jn], ad[im], bv[jn], acc2[im][jn]);
            }
            // Commit prefetched chunk into the other buffer
            if (kt < NKT - 1) {
                float* buf = ((kt + 1) & 1) ? cbs1 : cbs0;
#pragma unroll
                for (int j = 0; j < 4; j++) {
                    float* d = buf + pf_c4[j] * 4 * CBS_LD + pf_np[j];
                    d[0] = pv[j].x; d[CBS_LD] = pv[j].y;
                    d[2 * CBS_LD] = pv[j].z; d[3 * CBS_LD] = pv[j].w;
                }
            }
            __syncthreads();
        }

        // Score + running argmax. Per-thread n strictly increases (jn asc,
        // lo before hi, nt asc), so strict '>' keeps first-index semantics.
#pragma unroll
        for (int jn = 0; jn < 4; jn++) {
            int n = n0 + tx * 8 + jn * 2;
            float cs0 = g_csq[n];
            float cs1 = g_csq[n + 1];
#pragma unroll
            for (int im = 0; im < 4; im++) {
                unsigned lo, hi;
                UNPACK2(lo, hi, acc2[im][jn]);
                float s0 = fmaf(-2.0f, __uint_as_float(lo), cs0);
                float s1 = fmaf(-2.0f, __uint_as_float(hi), cs1);
                if (s0 > bestv[im]) { bestv[im] = s0; besti[im] = n; }
                if (s1 > bestv[im]) { bestv[im] = s1; besti[im] = n + 1; }
            }
        }
    }

    // Cross-tx reduction with lowest-index tie-break (matches jnp.argmax)
    __syncthreads();
#pragma unroll
    for (int im = 0; im < 4; im++) {
        int row = ty * 4 + im;
        rval[row * 16 + tx] = bestv[im];
        ridx[row * 16 + tx] = besti[im];
    }
    __syncthreads();
    if (tid < TM) {
        float bv = -3.0e38f; int bi = 0x7fffffff;
#pragma unroll
        for (int t = 0; t < 16; t++) {
            float v = rval[tid * 16 + t];
            int   i = ridx[tid * 16 + t];
            if (v > bv || (v == bv && i < bi)) { bv = v; bi = i; }
        }
        int q = b * LL + l0 + tid;
        g_pmax[split][q] = bv;
        g_pidx[split][q] = bi;
    }
}

// ---------------------------------------------------------------------------
// Kernel 2: combine splits -> code; gather emb (B,C,L); per-block loss partial
//   grid: NQ/8 blocks, 256 threads (warp per query)
// ---------------------------------------------------------------------------
__global__ void gather_kernel(const float* __restrict__ x,
                              const float* __restrict__ cb,
                              float* __restrict__ out) {
    __shared__ float ws[8];
    const int wid = threadIdx.x >> 5, lane = threadIdx.x & 31;
    const int q = blockIdx.x * 8 + wid;

    float bv = g_pmax[0][q]; int code = g_pidx[0][q];
#pragma unroll
    for (int s = 1; s < NSPLIT; s++) {
        float v = g_pmax[s][q]; int i = g_pidx[s][q];
        if (v > bv || (v == bv && i < code)) { bv = v; code = i; }
    }

    if (lane == 0) out[q] = (float)code;          // code region [0, NQ)

    const int b = q >> 11;          // / LL
    const int l = q & 2047;
    const float* crow = cb + (size_t)code * CC;
    float* emb = out + NQ;
    float lsum = 0.f;
#pragma unroll
    for (int j = 0; j < 8; j++) {
        int c = lane + j * 32;
        float e = crow[c];
        size_t pos = ((size_t)(b * CC + c)) * LL + l;
        emb[pos] = e;
        float d = x[pos] - e;
        lsum = fmaf(d, d, lsum);
    }
#pragma unroll
    for (int off = 16; off; off >>= 1)
        lsum += __shfl_xor_sync(0xffffffffu, lsum, off);
    if (lane == 0) ws[wid] = lsum;
    __syncthreads();
    if (threadIdx.x == 0) {
        float s = 0.f;
#pragma unroll
        for (int w = 0; w < 8; w++) s += ws[w];
        g_losspart[blockIdx.x] = s;              // deterministic: no atomics
    }
}

// ---------------------------------------------------------------------------
// Kernel 3: deterministic loss reduction
// ---------------------------------------------------------------------------
__global__ void loss_kernel(float* __restrict__ out) {
    __shared__ float s[256];
    float a = 0.f;
    for (int i = threadIdx.x; i < NQ / 8; i += 256) a += g_losspart[i];
    s[threadIdx.x] = a;
    __syncthreads();
    for (int off = 128; off; off >>= 1) {
        if (threadIdx.x < off) s[threadIdx.x] += s[threadIdx.x + off];
        __syncthreads();
    }
    if (threadIdx.x == 0)
        out[NQ + NEMB] = s[0] / (float)NEMB;
}

// ---------------------------------------------------------------------------
extern "C" void kernel_launch(void* const* d_in, const int* in_sizes, int n_in,
                              void* d_out, int out_size) {
    const float* x  = (const float*)d_in[0];
    const float* cb = (const float*)d_in[1];
    // Defensive: inputs expected in setup_inputs order (x=4194304, cb=2097152)
    if (n_in >= 2 && in_sizes[0] == KK * CC && in_sizes[1] == BB * CC * LL) {
        const float* t = x; x = cb; cb = t;
    }
    float* out = (float*)d_out;

    const size_t smem =
        (size_t)(CC * TM + 2 * KCH * CBS_LD + TM * 16) * 4 + (size_t)TM * 16 * 4;
    cudaFuncSetAttribute(dist_kernel, cudaFuncAttributeMaxDynamicSharedMemorySize,
                         (int)smem);

    csq_kernel<<<KK / 8, 256>>>(cb);
    dist_kernel<<<dim3(NQ / TM, NSPLIT), NTHREADS, smem>>>(x, cb);
    gather_kernel<<<NQ / 8, 256>>>(x, cb, out);
    loss_kernel<<<1, 256>>>(out);
    (void)out_size;
}

// round 4
// speedup vs baseline: 1.7781x; 1.7781x over previous
#include <cuda_runtime.h>
#include <cstddef>

typedef unsigned int u32;

// Problem shape
#define BBATCH 8
#define CC   256
#define LL   2048
#define KK   8192
#define NQ   16384               // B*L queries
#define NEMB (BBATCH*CC*LL)      // 4194304
#define NMT  128                 // m-tiles of 128 queries
#define NNT  64                  // n-tiles of 128 codes
#define EPS_GAP 0.05f            // rescan threshold on top-2 score gap

// Static scratch (no allocation anywhere)
__device__ float g_Ah[NMT*32*8*128];   // x hi, mma-fragment layout (16.8MB)
__device__ float g_Al[NMT*32*8*128];   // x lo
__device__ float g_Bh[NNT*32*16*64];   // cb hi (8.4MB)
__device__ float g_Bl[NNT*32*16*64];   // cb lo
__device__ float g_csq[KK];
__device__ float g_pval[NNT][NQ];      // per-ntile best value
__device__ int   g_pidx[NNT][NQ];      // per-ntile best index
__device__ float g_pv2[NNT][NQ];       // per-ntile second-best value
__device__ int   g_code[NQ];
__device__ int   g_rlist[NQ];
__device__ int   g_rcount;
__device__ float g_losspart[NQ/8];

__device__ __forceinline__ float tf32_rna(float v) {
    u32 r; asm("cvt.rna.tf32.f32 %0, %1;" : "=r"(r) : "f"(v));
    return __uint_as_float(r);
}

#define MMA_TF32(d, a, b) \
    asm volatile("mma.sync.aligned.m16n8k8.row.col.f32.tf32.tf32.f32 " \
        "{%0,%1,%2,%3},{%4,%5,%6,%7},{%8,%9},{%0,%1,%2,%3};" \
        : "+f"(d[0]), "+f"(d[1]), "+f"(d[2]), "+f"(d[3]) \
        : "r"((a).x), "r"((a).y), "r"((a).z), "r"((a).w), \
          "r"((b).x), "r"((b).y))

__device__ __forceinline__ void cpa16(u32 dst, const float* src) {
    asm volatile("cp.async.cg.shared.global [%0], [%1], 16;"
                 :: "r"(dst), "l"(src));
}

// ---------------------------------------------------------------------------
// Kernel 0: per-code squared norms (+ zero the rescan counter)
// ---------------------------------------------------------------------------
__global__ void csq_kernel(const float* __restrict__ cb) {
    if (blockIdx.x == 0 && threadIdx.x == 0) g_rcount = 0;
    int w = threadIdx.x >> 5, lane = threadIdx.x & 31;
    int row = blockIdx.x * 8 + w;
    const float* r = cb + (size_t)row * CC;
    float s = 0.f;
#pragma unroll
    for (int j = 0; j < 8; j++) { float v = r[lane + j*32]; s = fmaf(v, v, s); }
#pragma unroll
    for (int off = 16; off; off >>= 1) s += __shfl_xor_sync(0xffffffffu, s, off);
    if (lane == 0) g_csq[row] = s;
}

// ---------------------------------------------------------------------------
// Prep: split x into tf32 hi/lo in A-fragment layout.
// ---------------------------------------------------------------------------
__global__ void prep_x(const float* __restrict__ x) {
    int t = blockIdx.x * 256 + threadIdx.x;
    int lane = t & 31, msub = (t >> 5) & 7, kc = (t >> 8) & 31, mtile = t >> 13;
    int r0 = lane >> 2, kk0 = lane & 3;
    float h[4], l[4];
#pragma unroll
    for (int e = 0; e < 4; e++) {
        int r  = r0 + (e & 1) * 8;
        int kk = kk0 + ((e >> 1) & 1) * 4;
        int q  = mtile * 128 + msub * 16 + r;
        int c  = kc * 8 + kk;
        int b  = q >> 11, li = q & 2047;
        float v  = x[((size_t)b * CC + c) * LL + li];
        float hi = tf32_rna(v);
        h[e] = hi; l[e] = tf32_rna(v - hi);
    }
    *(float4*)(g_Ah + (size_t)t * 4) = make_float4(h[0], h[1], h[2], h[3]);
    *(float4*)(g_Al + (size_t)t * 4) = make_float4(l[0], l[1], l[2], l[3]);
}

// ---------------------------------------------------------------------------
// Prep: split codebook into tf32 hi/lo in B-fragment layout.
// ---------------------------------------------------------------------------
__global__ void prep_cb(const float* __restrict__ cb) {
    int t = blockIdx.x * 256 + threadIdx.x;
    int lane = t & 31, nsub = (t >> 5) & 15, kc = (t >> 9) & 31, ntile = t >> 14;
    int n  = ntile * 128 + nsub * 8 + (lane >> 2);
    int c0 = kc * 8 + (lane & 3);
    float v0 = cb[(size_t)n * CC + c0];
    float v1 = cb[(size_t)n * CC + c0 + 4];
    float h0 = tf32_rna(v0), h1 = tf32_rna(v1);
    *(float2*)(g_Bh + (size_t)t * 2) = make_float2(h0, h1);
    *(float2*)(g_Bl + (size_t)t * 2) = make_float2(tf32_rna(v0 - h0), tf32_rna(v1 - h1));
}

// ---------------------------------------------------------------------------
// GEMM: 3xTF32 mma + fused top-2 argmax of (csq - 2*dot).
// ---------------------------------------------------------------------------
__device__ __forceinline__ void stage_chunk(u32 sb, int g,
        const float* Agh, const float* Agl,
        const float* Bgh, const float* Bgl, int tid) {
    u32 d = sb + (u32)(g & 1) * 65536u;
    const float* s0 = Agh + g * 4096;
    const float* s1 = Agl + g * 4096;
    const float* s2 = Bgh + g * 4096;
    const float* s3 = Bgl + g * 4096;
#pragma unroll
    for (int k = 0; k < 4; k++) {
        int i = tid + k * 256;
        cpa16(d +          i * 16, s0 + i * 4);
        cpa16(d + 16384u + i * 16, s1 + i * 4);
        cpa16(d + 32768u + i * 16, s2 + i * 4);
        cpa16(d + 49152u + i * 16, s3 + i * 4);
    }
    asm volatile("cp.async.commit_group;");
}

__global__ void __launch_bounds__(256, 1) gemm_kernel() {
    extern __shared__ float sm[];
    const int tid = threadIdx.x, lane = tid & 31, warp = tid >> 5;
    const int wm = warp & 1, wn = warp >> 1;
    const int bm = blockIdx.x, bn = blockIdx.y;
    const float* Agh = g_Ah + (size_t)bm * 32768;
    const float* Agl = g_Al + (size_t)bm * 32768;
    const float* Bgh = g_Bh + (size_t)bn * 32768;
    const float* Bgl = g_Bl + (size_t)bn * 32768;
    u32 sb = (u32)__cvta_generic_to_shared(sm);

    float acc[4][4][4];
#pragma unroll
    for (int i = 0; i < 4; i++)
#pragma unroll
        for (int j = 0; j < 4; j++)
#pragma unroll
            for (int e = 0; e < 4; e++) acc[i][j][e] = 0.f;

    stage_chunk(sb, 0, Agh, Agl, Bgh, Bgl, tid);

#pragma unroll 1
    for (int g = 0; g < 8; g++) {
        if (g < 7) {
            stage_chunk(sb, g + 1, Agh, Agl, Bgh, Bgl, tid);
            asm volatile("cp.async.wait_group 1;");
        } else {
            asm volatile("cp.async.wait_group 0;");
        }
        __syncthreads();
        const float* buf  = sm + (g & 1) * 16384;
        const float* As_h = buf;
        const float* As_l = buf + 4096;
        const float* Bs_h = buf + 8192;
        const float* Bs_l = buf + 12288;
#pragma unroll
        for (int kc = 0; kc < 4; kc++) {
            uint4 ah[4], al[4]; uint2 bh[4], bl[4];
#pragma unroll
            for (int i = 0; i < 4; i++) {
                int mo = ((kc * 8 + wm * 4 + i) * 32 + lane) * 4;
                ah[i] = *(const uint4*)(As_h + mo);
                al[i] = *(const uint4*)(As_l + mo);
                int no = ((kc * 16 + wn * 4 + i) * 32 + lane) * 2;
                bh[i] = *(const uint2*)(Bs_h + no);
                bl[i] = *(const uint2*)(Bs_l + no);
            }
#pragma unroll
            for (int i = 0; i < 4; i++)
#pragma unroll
                for (int j = 0; j < 4; j++) {
                    MMA_TF32(acc[i][j], ah[i], bh[j]);
                    MMA_TF32(acc[i][j], ah[i], bl[j]);
                    MMA_TF32(acc[i][j], al[i], bh[j]);
                }
        }
        __syncthreads();
    }

    // Epilogue: top-2 of score = csq[n] - 2*dot per m-row; first-index ties.
    float bv[4][2]; int bi[4][2]; float b2[4][2];
#pragma unroll
    for (int i = 0; i < 4; i++)
#pragma unroll
        for (int h = 0; h < 2; h++) {
            bv[i][h] = -3.0e38f; bi[i][h] = 0x7fffffff; b2[i][h] = -3.0e38f;
        }

#define UPD(i, h, s, n) do { \
    if ((s) > bv[i][h]) { b2[i][h] = bv[i][h]; bv[i][h] = (s); bi[i][h] = (n); } \
    else b2[i][h] = fmaxf(b2[i][h], (s)); } while (0)

#pragma unroll
    for (int j = 0; j < 4; j++) {                  // n ascending across j
        int n0 = bn * 128 + wn * 32 + j * 8 + (lane & 3) * 2;
        float cs0 = g_csq[n0], cs1 = g_csq[n0 + 1];
#pragma unroll
        for (int i = 0; i < 4; i++) {
            float s0 = fmaf(-2.f, acc[i][j][0], cs0);  UPD(i, 0, s0, n0);
            float s1 = fmaf(-2.f, acc[i][j][1], cs1);  UPD(i, 0, s1, n0 + 1);
            float s2 = fmaf(-2.f, acc[i][j][2], cs0);  UPD(i, 1, s2, n0);
            float s3 = fmaf(-2.f, acc[i][j][3], cs1);  UPD(i, 1, s3, n0 + 1);
        }
    }
    // butterfly over lane%4 (disjoint n, same rows): merge top-2 sets
#pragma unroll
    for (int off = 1; off <= 2; off <<= 1)
#pragma unroll
        for (int i = 0; i < 4; i++)
#pragma unroll
            for (int h = 0; h < 2; h++) {
                float ov  = __shfl_xor_sync(0xffffffffu, bv[i][h], off);
                int   oi  = __shfl_xor_sync(0xffffffffu, bi[i][h], off);
                float ov2 = __shfl_xor_sync(0xffffffffu, b2[i][h], off);
                if (ov > bv[i][h] || (ov == bv[i][h] && oi < bi[i][h])) {
                    b2[i][h] = fmaxf(bv[i][h], ov2);
                    bv[i][h] = ov; bi[i][h] = oi;
                } else {
                    b2[i][h] = fmaxf(b2[i][h], ov);
                }
            }
    // smem reduce across the 4 n-warp-columns
    float* rv  = sm;                   // [4][128]
    int*   ri  = (int*)(sm + 512);     // [4][128]
    float* rv2 = sm + 1024;            // [4][128]
    if ((lane & 3) == 0) {
        int r = lane >> 2;
#pragma unroll
        for (int i = 0; i < 4; i++)
#pragma unroll
            for (int h = 0; h < 2; h++) {
                int ml = wm * 64 + i * 16 + h * 8 + r;
                rv [wn * 128 + ml] = bv[i][h];
                ri [wn * 128 + ml] = bi[i][h];
                rv2[wn * 128 + ml] = b2[i][h];
            }
    }
    __syncthreads();
    if (tid < 128) {
        float v = rv[tid]; int ix = ri[tid]; float v2 = rv2[tid];
#pragma unroll
        for (int w = 1; w < 4; w++) {              // wn ascending = n ascending
            float ov = rv[w * 128 + tid]; int oi = ri[w * 128 + tid];
            float ov2 = rv2[w * 128 + tid];
            if (ov > v || (ov == v && oi < ix)) {
                v2 = fmaxf(v, ov2); v = ov; ix = oi;
            } else {
                v2 = fmaxf(v2, ov);
            }
        }
        int q = bm * 128 + tid;
        g_pval[bn][q] = v;
        g_pidx[bn][q] = ix;
        g_pv2 [bn][q] = v2;
    }
}

// ---------------------------------------------------------------------------
// Combine partials -> code; flag small-gap queries for exact rescan
// ---------------------------------------------------------------------------
__global__ void combine_kernel() {
    int q = blockIdx.x * 256 + threadIdx.x;
    float v = g_pval[0][q]; int ix = g_pidx[0][q]; float v2 = g_pv2[0][q];
#pragma unroll 8
    for (int s = 1; s < NNT; s++) {                // ascending n blocks
        float ov = g_pval[s][q]; int oi = g_pidx[s][q]; float ov2 = g_pv2[s][q];
        if (ov > v || (ov == v && oi < ix)) {
            v2 = fmaxf(v, ov2); v = ov; ix = oi;
        } else {
            v2 = fmaxf(v2, ov);
        }
    }
    g_code[q] = ix;
    if (v - v2 < EPS_GAP) {
        int slot = atomicAdd(&g_rcount, 1);
        g_rlist[slot] = q;
    }
}

// ---------------------------------------------------------------------------
// Exact rescan: for flagged queries, recompute argmax in exact fp32 with the
// SAME arithmetic order as the round-2 scalar kernel (verified rel_err 0.0):
// sequential fmaf over c = 0..255, score = fmaf(-2, dot, csq[n]).
// ---------------------------------------------------------------------------
__global__ void rescan_kernel(const float* __restrict__ x,
                              const float* __restrict__ cb) {
    __shared__ float xq[CC];
    __shared__ float sv[256];
    __shared__ int   si[256];
    const int tid = threadIdx.x;
    const int count = g_rcount;

    for (int it = blockIdx.x; it < count; it += gridDim.x) {
        const int q = g_rlist[it];
        const int b = q >> 11, l = q & 2047;
        xq[tid] = x[((size_t)(b * CC + tid)) * LL + l];
        __syncthreads();

        float bv = -3.0e38f; int bi = 0x7fffffff;
#pragma unroll 4
        for (int jj = 0; jj < 32; jj++) {
            int n = tid * 32 + jj;
            const float* row = cb + (size_t)n * CC;
            float acc = 0.f;
#pragma unroll
            for (int c4 = 0; c4 < CC / 4; c4++) {
                float4 v = *(const float4*)(row + c4 * 4);
                acc = fmaf(xq[c4 * 4 + 0], v.x, acc);
                acc = fmaf(xq[c4 * 4 + 1], v.y, acc);
                acc = fmaf(xq[c4 * 4 + 2], v.z, acc);
                acc = fmaf(xq[c4 * 4 + 3], v.w, acc);
            }
            float s = fmaf(-2.f, acc, g_csq[n]);
            if (s > bv) { bv = s; bi = n; }        // ascending n: strict >
        }
        sv[tid] = bv; si[tid] = bi;
        __syncthreads();
        for (int off = 128; off; off >>= 1) {
            if (tid < off) {
                float ov = sv[tid + off]; int oi = si[tid + off];
                if (ov > sv[tid] || (ov == sv[tid] && oi < si[tid])) {
                    sv[tid] = ov; si[tid] = oi;
                }
            }
            __syncthreads();
        }
        if (tid == 0) g_code[q] = si[0];
        __syncthreads();
    }
}

// ---------------------------------------------------------------------------
// Gather emb (B,C,L) from final codes; per-block loss partial
// ---------------------------------------------------------------------------
__global__ void gather_kernel(const float* __restrict__ x,
                              const float* __restrict__ cb,
                              float* __restrict__ out) {
    __shared__ float ws[8];
    const int wid = threadIdx.x >> 5, lane = threadIdx.x & 31;
    const int q = blockIdx.x * 8 + wid;
    const int code = g_code[q];

    if (lane == 0) out[q] = (float)code;

    const int b = q >> 11, l = q & 2047;
    const float* crow = cb + (size_t)code * CC;
    float* emb = out + NQ;
    float lsum = 0.f;
#pragma unroll
    for (int j = 0; j < 8; j++) {
        int c = lane + j * 32;
        float e = crow[c];
        size_t pos = ((size_t)(b * CC + c)) * LL + l;
        emb[pos] = e;
        float d = x[pos] - e;
        lsum = fmaf(d, d, lsum);
    }
#pragma unroll
    for (int off = 16; off; off >>= 1)
        lsum += __shfl_xor_sync(0xffffffffu, lsum, off);
    if (lane == 0) ws[wid] = lsum;
    __syncthreads();
    if (threadIdx.x == 0) {
        float s = 0.f;
#pragma unroll
        for (int w = 0; w < 8; w++) s += ws[w];
        g_losspart[blockIdx.x] = s;
    }
}

__global__ void loss_kernel(float* __restrict__ out) {
    __shared__ float s[256];
    float a = 0.f;
    for (int i = threadIdx.x; i < NQ / 8; i += 256) a += g_losspart[i];
    s[threadIdx.x] = a;
    __syncthreads();
    for (int off = 128; off; off >>= 1) {
        if (threadIdx.x < off) s[threadIdx.x] += s[threadIdx.x + off];
        __syncthreads();
    }
    if (threadIdx.x == 0) out[NQ + NEMB] = s[0] / (float)NEMB;
}

// ---------------------------------------------------------------------------
extern "C" void kernel_launch(void* const* d_in, const int* in_sizes, int n_in,
                              void* d_out, int out_size) {
    const float* x  = (const float*)d_in[0];
    const float* cb = (const float*)d_in[1];
    if (n_in >= 2 && in_sizes[0] == KK * CC && in_sizes[1] == BBATCH * CC * LL) {
        const float* t = x; x = cb; cb = t;
    }
    float* out = (float*)d_out;

    cudaFuncSetAttribute(gemm_kernel,
        cudaFuncAttributeMaxDynamicSharedMemorySize, 131072);

    csq_kernel<<<KK / 8, 256>>>(cb);
    prep_x<<<4096, 256>>>(x);
    prep_cb<<<4096, 256>>>(cb);
    gemm_kernel<<<dim3(NMT, NNT), 256, 131072>>>();
    combine_kernel<<<NQ / 256, 256>>>();
    rescan_kernel<<<128, 256>>>(x, cb);
    gather_kernel<<<NQ / 8, 256>>>(x, cb, out);
    loss_kernel<<<1, 256>>>(out);
    (void)out_size;
}

// round 6
// speedup vs baseline: 2.8937x; 1.6273x over previous
#include <cuda_runtime.h>
#include <cuda_fp16.h>
#include <cstddef>

typedef unsigned int u32;

// Problem shape
#define BBATCH 8
#define CC   256
#define LL   2048
#define KK   8192
#define NQ   16384
#define NEMB (BBATCH*CC*LL)
#define NMT  128              // m-tiles of 128 queries
#define NNT  64               // n-tiles of 128 codes
#define NG   8                // k-chunks of 32 (staged)
#define EPS_GAP 0.02f

// Per-(tile,g) slab: A: [kc2][msub8][lane32][uint4] = 8192 B
//                    B: [kc2][nsub16][lane32][uint2] = 8192 B
#define SLAB_B 8192
#define STAGE_B 32768         // Ah|Al|Bh|Bl per stage (8KB each)

// Static scratch (fragment-major fp16 hi/lo slabs)
__device__ __align__(16) u32 g_Ah[NMT*NG*SLAB_B/4];   // 8MB
__device__ __align__(16) u32 g_Al[NMT*NG*SLAB_B/4];
__device__ __align__(16) u32 g_Bh[NNT*NG*SLAB_B/4];   // 4MB
__device__ __align__(16) u32 g_Bl[NNT*NG*SLAB_B/4];
__device__ float g_csq[KK];
__device__ float g_pval[NNT][NQ];
__device__ int   g_pidx[NNT][NQ];
__device__ float g_pv2[NNT][NQ];
__device__ int   g_code[NQ];
__device__ int   g_rlist[NQ];
__device__ int   g_rcount;
__device__ float g_losspart[NQ/8];

// m16n8k16 f16 mma, fp32 accumulate
#define MMA_F16(d, a, b) \
    asm volatile("mma.sync.aligned.m16n8k16.row.col.f32.f16.f16.f32 " \
        "{%0,%1,%2,%3},{%4,%5,%6,%7},{%8,%9},{%0,%1,%2,%3};" \
        : "+f"(d[0]), "+f"(d[1]), "+f"(d[2]), "+f"(d[3]) \
        : "r"((a).x), "r"((a).y), "r"((a).z), "r"((a).w), \
          "r"((b).x), "r"((b).y))

__device__ __forceinline__ void cpa16(u32 dst, const void* src) {
    asm volatile("cp.async.cg.shared.global [%0], [%1], 16;" :: "r"(dst), "l"(src));
}
__device__ __forceinline__ u32 pack_half2(float v0, float v1, float* r0, float* r1) {
    __half h0 = __float2half(v0), h1 = __float2half(v1);
    *r0 = v0 - __half2float(h0);
    *r1 = v1 - __half2float(h1);
    return (u32)__half_as_ushort(h0) | ((u32)__half_as_ushort(h1) << 16);
}
__device__ __forceinline__ u32 pack_half2_only(float v0, float v1) {
    __half h0 = __float2half(v0), h1 = __float2half(v1);
    return (u32)__half_as_ushort(h0) | ((u32)__half_as_ushort(h1) << 16);
}

// ---------------------------------------------------------------------------
// Kernel 0: per-code squared norms (+ zero rescan counter)
// ---------------------------------------------------------------------------
__global__ void csq_kernel(const float* __restrict__ cb) {
    if (blockIdx.x == 0 && threadIdx.x == 0) g_rcount = 0;
    int w = threadIdx.x >> 5, lane = threadIdx.x & 31;
    int row = blockIdx.x * 8 + w;
    const float* r = cb + (size_t)row * CC;
    float s = 0.f;
#pragma unroll
    for (int j = 0; j < 8; j++) { float v = r[lane + j*32]; s = fmaf(v, v, s); }
#pragma unroll
    for (int off = 16; off; off >>= 1) s += __shfl_xor_sync(0xffffffffu, s, off);
    if (lane == 0) g_csq[row] = s;
}

// ---------------------------------------------------------------------------
// Prep: x -> fp16 hi/lo A-fragment slabs.
// A frag (m16n8k16): reg e holds (r = lane/4 + (e&1)*8, k = (lane%4)*2 + (e>>1)*8)
// with elements k (lo16) and k+1 (hi16).
// ---------------------------------------------------------------------------
__global__ void prep_x(const float* __restrict__ x) {
    int t = blockIdx.x * 256 + threadIdx.x;     // 524288
    int lane = t & 31, msub = (t >> 5) & 7, kc = (t >> 8) & 1;
    int g = (t >> 9) & 7, mtile = t >> 12;
    u32 ph[4], pl[4];
#pragma unroll
    for (int e = 0; e < 4; e++) {
        int r  = (lane >> 2) + (e & 1) * 8;
        int k  = g * 32 + kc * 16 + (lane & 3) * 2 + ((e >> 1) & 1) * 8;
        int q  = mtile * 128 + msub * 16 + r;
        int b  = q >> 11, l = q & 2047;
        float v0 = x[((size_t)(b * CC + k    )) * LL + l];
        float v1 = x[((size_t)(b * CC + k + 1)) * LL + l];
        float r0, r1;
        ph[e] = pack_half2(v0, v1, &r0, &r1);
        pl[e] = pack_half2_only(r0, r1);
    }
    size_t idx = ((size_t)(((mtile * 8 + g) * 2 + kc) * 8 + msub) * 32 + lane);
    ((uint4*)g_Ah)[idx] = make_uint4(ph[0], ph[1], ph[2], ph[3]);
    ((uint4*)g_Al)[idx] = make_uint4(pl[0], pl[1], pl[2], pl[3]);
}

// ---------------------------------------------------------------------------
// Prep: codebook -> fp16 hi/lo B-fragment slabs.
// B frag: reg e holds (n = lane/4, k = (lane%4)*2 + e*8) elems k, k+1.
// ---------------------------------------------------------------------------
__global__ void prep_cb(const float* __restrict__ cb) {
    int t = blockIdx.x * 256 + threadIdx.x;     // 524288
    int lane = t & 31, nsub = (t >> 5) & 15, kc = (t >> 9) & 1;
    int g = (t >> 10) & 7, ntile = t >> 13;
    int n = ntile * 128 + nsub * 8 + (lane >> 2);
    u32 ph[2], pl[2];
#pragma unroll
    for (int e = 0; e < 2; e++) {
        int k = g * 32 + kc * 16 + (lane & 3) * 2 + e * 8;
        float v0 = cb[(size_t)n * CC + k];
        float v1 = cb[(size_t)n * CC + k + 1];
        float r0, r1;
        ph[e] = pack_half2(v0, v1, &r0, &r1);
        pl[e] = pack_half2_only(r0, r1);
    }
    size_t idx = ((size_t)(((ntile * 8 + g) * 2 + kc) * 16 + nsub) * 32 + lane);
    ((uint2*)g_Bh)[idx] = make_uint2(ph[0], ph[1]);
    ((uint2*)g_Bl)[idx] = make_uint2(pl[0], pl[1]);
}

// ---------------------------------------------------------------------------
// GEMM: 3-term fp16 split mma (ah*bh + ah*bl + al*bh), fused top-2 argmax.
//   grid (128, 64), 256 threads; block tile 128x128, warp tile 64x32.
//   Smem: 2 x 32KB stages [Ah 8K|Al 8K|Bh 8K|Bl 8K], cp.async pipelined.
// ---------------------------------------------------------------------------
__device__ __forceinline__ void stage_chunk(u32 sb, int buf, int bm, int bn,
                                            int g, int tid) {
    u32 d = sb + (u32)buf * STAGE_B;
    const char* ah = (const char*)g_Ah + (size_t)(bm * 8 + g) * SLAB_B;
    const char* al = (const char*)g_Al + (size_t)(bm * 8 + g) * SLAB_B;
    const char* bh = (const char*)g_Bh + (size_t)(bn * 8 + g) * SLAB_B;
    const char* bl = (const char*)g_Bl + (size_t)(bn * 8 + g) * SLAB_B;
#pragma unroll
    for (int j = 0; j < 2; j++) {
        int i = (tid + j * 256) * 16;
        cpa16(d +          i, ah + i);
        cpa16(d +  8192u + i, al + i);
        cpa16(d + 16384u + i, bh + i);
        cpa16(d + 24576u + i, bl + i);
    }
    asm volatile("cp.async.commit_group;" ::: "memory");
}

__global__ void __launch_bounds__(256) gemm_kernel() {
    extern __shared__ __align__(16) char smem[];
    float* sm = (float*)smem;
    const u32 sb = (u32)__cvta_generic_to_shared(smem);
    const int tid = threadIdx.x, lane = tid & 31, warp = tid >> 5;
    const int wm = warp & 1, wn = warp >> 1;       // 2 x 4 warp grid
    const int bm = blockIdx.x, bn = blockIdx.y;

    float acc[4][4][4];
#pragma unroll
    for (int i = 0; i < 4; i++)
#pragma unroll
        for (int j = 0; j < 4; j++)
#pragma unroll
            for (int e = 0; e < 4; e++) acc[i][j][e] = 0.f;

    stage_chunk(sb, 0, bm, bn, 0, tid);
    stage_chunk(sb, 1, bm, bn, 1, tid);

#pragma unroll 1
    for (int g = 0; g < NG; g++) {
        if (g < NG - 1) asm volatile("cp.async.wait_group 1;" ::: "memory");
        else            asm volatile("cp.async.wait_group 0;" ::: "memory");
        __syncthreads();
        const char* buf = smem + (g & 1) * STAGE_B;
#pragma unroll
        for (int kc = 0; kc < 2; kc++) {
            uint4 ah[4], al[4]; uint2 bh[4], bl[4];
#pragma unroll
            for (int i = 0; i < 4; i++) {
                int mo = ((kc * 8 + wm * 4 + i) * 32 + lane) * 16;
                ah[i] = *(const uint4*)(buf + mo);
                al[i] = *(const uint4*)(buf + 8192 + mo);
                int no = ((kc * 16 + wn * 4 + i) * 32 + lane) * 8;
                bh[i] = *(const uint2*)(buf + 16384 + no);
                bl[i] = *(const uint2*)(buf + 24576 + no);
            }
#pragma unroll
            for (int i = 0; i < 4; i++)
#pragma unroll
                for (int j = 0; j < 4; j++) {
                    MMA_F16(acc[i][j], ah[i], bh[j]);
                    MMA_F16(acc[i][j], ah[i], bl[j]);
                    MMA_F16(acc[i][j], al[i], bh[j]);
                }
        }
        __syncthreads();
        if (g < NG - 2) stage_chunk(sb, g & 1, bm, bn, g + 2, tid);
    }

    // Epilogue: top-2 of score = csq[n] - 2*dot per m-row; first-index ties.
    // C frag: e0/e1 -> (r, n0/n0+1); e2/e3 -> (r+8, n0/n0+1).
    float bv[4][2]; int bi[4][2]; float b2[4][2];
#pragma unroll
    for (int i = 0; i < 4; i++)
#pragma unroll
        for (int h = 0; h < 2; h++) {
            bv[i][h] = -3.0e38f; bi[i][h] = 0x7fffffff; b2[i][h] = -3.0e38f;
        }

#define UPD(i, h, s, n) do { \
    if ((s) > bv[i][h]) { b2[i][h] = bv[i][h]; bv[i][h] = (s); bi[i][h] = (n); } \
    else b2[i][h] = fmaxf(b2[i][h], (s)); } while (0)

#pragma unroll
    for (int j = 0; j < 4; j++) {                  // n ascending across j
        int n0 = bn * 128 + wn * 32 + j * 8 + (lane & 3) * 2;
        float cs0 = g_csq[n0], cs1 = g_csq[n0 + 1];
#pragma unroll
        for (int i = 0; i < 4; i++) {
            float s0 = fmaf(-2.f, acc[i][j][0], cs0);  UPD(i, 0, s0, n0);
            float s1 = fmaf(-2.f, acc[i][j][1], cs1);  UPD(i, 0, s1, n0 + 1);
            float s2 = fmaf(-2.f, acc[i][j][2], cs0);  UPD(i, 1, s2, n0);
            float s3 = fmaf(-2.f, acc[i][j][3], cs1);  UPD(i, 1, s3, n0 + 1);
        }
    }
    // butterfly over lane%4 (disjoint n, same rows): merge top-2 sets
#pragma unroll
    for (int off = 1; off <= 2; off <<= 1)
#pragma unroll
        for (int i = 0; i < 4; i++)
#pragma unroll
            for (int h = 0; h < 2; h++) {
                float ov  = __shfl_xor_sync(0xffffffffu, bv[i][h], off);
                int   oi  = __shfl_xor_sync(0xffffffffu, bi[i][h], off);
                float ov2 = __shfl_xor_sync(0xffffffffu, b2[i][h], off);
                if (ov > bv[i][h] || (ov == bv[i][h] && oi < bi[i][h])) {
                    b2[i][h] = fmaxf(bv[i][h], ov2);
                    bv[i][h] = ov; bi[i][h] = oi;
                } else {
                    b2[i][h] = fmaxf(b2[i][h], ov);
                }
            }
    // smem reduce across the 4 n-warp-columns
    float* rv  = sm;                   // [4][128]
    int*   ri  = (int*)(sm + 512);     // [4][128]
    float* rv2 = sm + 1024;            // [4][128]
    if ((lane & 3) == 0) {
        int r = lane >> 2;
#pragma unroll
        for (int i = 0; i < 4; i++)
#pragma unroll
            for (int h = 0; h < 2; h++) {
                int ml = wm * 64 + i * 16 + h * 8 + r;
                rv [wn * 128 + ml] = bv[i][h];
                ri [wn * 128 + ml] = bi[i][h];
                rv2[wn * 128 + ml] = b2[i][h];
            }
    }
    __syncthreads();
    if (tid < 128) {
        float v = rv[tid]; int ix = ri[tid]; float v2 = rv2[tid];
#pragma unroll
        for (int w = 1; w < 4; w++) {              // wn ascending = n ascending
            float ov = rv[w * 128 + tid]; int oi = ri[w * 128 + tid];
            float ov2 = rv2[w * 128 + tid];
            if (ov > v || (ov == v && oi < ix)) { v2 = fmaxf(v, ov2); v = ov; ix = oi; }
            else v2 = fmaxf(v2, ov);
        }
        int q = bm * 128 + tid;
        g_pval[bn][q] = v;
        g_pidx[bn][q] = ix;
        g_pv2 [bn][q] = v2;
    }
}

// ---------------------------------------------------------------------------
// Combine partials -> code; flag small-gap queries for exact rescan
// ---------------------------------------------------------------------------
__global__ void combine_kernel() {
    int q = blockIdx.x * 256 + threadIdx.x;
    float v = g_pval[0][q]; int ix = g_pidx[0][q]; float v2 = g_pv2[0][q];
#pragma unroll 8
    for (int s = 1; s < NNT; s++) {                // ascending n blocks
        float ov = g_pval[s][q]; int oi = g_pidx[s][q]; float ov2 = g_pv2[s][q];
        if (ov > v || (ov == v && oi < ix)) { v2 = fmaxf(v, ov2); v = ov; ix = oi; }
        else v2 = fmaxf(v2, ov);
    }
    g_code[q] = ix;
    if (v - v2 < EPS_GAP) {
        int slot = atomicAdd(&g_rcount, 1);
        g_rlist[slot] = q;
    }
}

// ---------------------------------------------------------------------------
// Exact rescan (bit-identical to the verified round-2 scalar argmax)
// ---------------------------------------------------------------------------
__global__ void rescan_kernel(const float* __restrict__ x,
                              const float* __restrict__ cb) {
    __shared__ float xq[CC];
    __shared__ float sv[256];
    __shared__ int   si[256];
    const int tid = threadIdx.x;
    const int count = g_rcount;

    for (int it = blockIdx.x; it < count; it += gridDim.x) {
        const int q = g_rlist[it];
        const int b = q >> 11, l = q & 2047;
        xq[tid] = x[((size_t)(b * CC + tid)) * LL + l];
        __syncthreads();

        float bv = -3.0e38f; int bi = 0x7fffffff;
#pragma unroll 4
        for (int jj = 0; jj < 32; jj++) {
            int n = tid * 32 + jj;
            const float* row = cb + (size_t)n * CC;
            float acc = 0.f;
#pragma unroll
            for (int c4 = 0; c4 < CC / 4; c4++) {
                float4 v = *(const float4*)(row + c4 * 4);
                acc = fmaf(xq[c4 * 4 + 0], v.x, acc);
                acc = fmaf(xq[c4 * 4 + 1], v.y, acc);
                acc = fmaf(xq[c4 * 4 + 2], v.z, acc);
                acc = fmaf(xq[c4 * 4 + 3], v.w, acc);
            }
            float s = fmaf(-2.f, acc, g_csq[n]);
            if (s > bv) { bv = s; bi = n; }
        }
        sv[tid] = bv; si[tid] = bi;
        __syncthreads();
        for (int off = 128; off; off >>= 1) {
            if (tid < off) {
                float ov = sv[tid + off]; int oi = si[tid + off];
                if (ov > sv[tid] || (ov == sv[tid] && oi < si[tid])) {
                    sv[tid] = ov; si[tid] = oi;
                }
            }
            __syncthreads();
        }
        if (tid == 0) g_code[q] = si[0];
        __syncthreads();
    }
}

// ---------------------------------------------------------------------------
// Gather emb (B,C,L); per-block loss partial; final loss
// ---------------------------------------------------------------------------
__global__ void gather_kernel(const float* __restrict__ x,
                              const float* __restrict__ cb,
                              float* __restrict__ out) {
    __shared__ float ws[8];
    const int wid = threadIdx.x >> 5, lane = threadIdx.x & 31;
    const int q = blockIdx.x * 8 + wid;
    const int code = g_code[q];
    if (lane == 0) out[q] = (float)code;

    const int b = q >> 11, l = q & 2047;
    const float* crow = cb + (size_t)code * CC;
    float* emb = out + NQ;
    float lsum = 0.f;
#pragma unroll
    for (int j = 0; j < 8; j++) {
        int c = lane + j * 32;
        float e = crow[c];
        size_t pos = ((size_t)(b * CC + c)) * LL + l;
        emb[pos] = e;
        float d = x[pos] - e;
        lsum = fmaf(d, d, lsum);
    }
#pragma unroll
    for (int off = 16; off; off >>= 1)
        lsum += __shfl_xor_sync(0xffffffffu, lsum, off);
    if (lane == 0) ws[wid] = lsum;
    __syncthreads();
    if (threadIdx.x == 0) {
        float s = 0.f;
#pragma unroll
        for (int w = 0; w < 8; w++) s += ws[w];
        g_losspart[blockIdx.x] = s;
    }
}

__global__ void loss_kernel(float* __restrict__ out) {
    __shared__ float s[256];
    float a = 0.f;
    for (int i = threadIdx.x; i < NQ / 8; i += 256) a += g_losspart[i];
    s[threadIdx.x] = a;
    __syncthreads();
    for (int off = 128; off; off >>= 1) {
        if (threadIdx.x < off) s[threadIdx.x] += s[threadIdx.x + off];
        __syncthreads();
    }
    if (threadIdx.x == 0) out[NQ + NEMB] = s[0] / (float)NEMB;
}

// ---------------------------------------------------------------------------
extern "C" void kernel_launch(void* const* d_in, const int* in_sizes, int n_in,
                              void* d_out, int out_size) {
    const float* x  = (const float*)d_in[0];
    const float* cb = (const float*)d_in[1];
    if (n_in >= 2 && in_sizes[0] == KK * CC && in_sizes[1] == BBATCH * CC * LL) {
        const float* t = x; x = cb; cb = t;
    }
    float* out = (float*)d_out;

    cudaFuncSetAttribute(gemm_kernel,
        cudaFuncAttributeMaxDynamicSharedMemorySize, 2 * STAGE_B);

    csq_kernel <<<KK / 8, 256>>>(cb);
    prep_x     <<<2048, 256>>>(x);
    prep_cb    <<<2048, 256>>>(cb);
    gemm_kernel<<<dim3(NMT, NNT), 256, 2 * STAGE_B>>>();
    combine_kernel<<<NQ / 256, 256>>>();
    rescan_kernel <<<256, 256>>>(x, cb);
    gather_kernel <<<NQ / 8, 256>>>(x, cb, out);
    loss_kernel   <<<1, 256>>>(out);
    (void)out_size;
}

// round 8
// speedup vs baseline: 3.0249x; 1.0454x over previous
#include <cuda_runtime.h>
#include <cuda_fp16.h>
#include <cstddef>

typedef unsigned int u32;

// Problem shape
#define BBATCH 8
#define CC   256
#define LL   2048
#define KK   8192
#define NQ   16384
#define NEMB (BBATCH*CC*LL)
#define NMT  128              // m-tiles of 128 queries
#define NNT  64               // n-tiles of 128 codes
#define NG   8                // k-chunks of 32 (staged)
#define EPS_GAP 0.02f

#define SLAB_B 8192           // per-(tile,g) fragment slab bytes
#define STAGE_B 32768         // Ah|Al|Bh|Bl per stage (8KB each)
#define NSTG 3

// Static scratch (fragment-major fp16 hi/lo slabs)
__device__ __align__(16) u32 g_Ah[NMT*NG*SLAB_B/4];   // 8MB
__device__ __align__(16) u32 g_Al[NMT*NG*SLAB_B/4];
__device__ __align__(16) u32 g_Bh[NNT*NG*SLAB_B/4];   // 4MB
__device__ __align__(16) u32 g_Bl[NNT*NG*SLAB_B/4];
__device__ float g_csq[KK];
__device__ float g_pval[NNT][NQ];
__device__ int   g_pidx[NNT][NQ];
__device__ float g_pv2[NNT][NQ];
__device__ int   g_code[NQ];
__device__ int   g_rlist[NQ];
__device__ int   g_rcount;
__device__ float g_losspart[NQ/32];

// m16n8k16 f16 mma, fp32 accumulate
#define MMA_F16(d, a, b) \
    asm volatile("mma.sync.aligned.m16n8k16.row.col.f32.f16.f16.f32 " \
        "{%0,%1,%2,%3},{%4,%5,%6,%7},{%8,%9},{%0,%1,%2,%3};" \
        : "+f"(d[0]), "+f"(d[1]), "+f"(d[2]), "+f"(d[3]) \
        : "r"((a).x), "r"((a).y), "r"((a).z), "r"((a).w), \
          "r"((b).x), "r"((b).y))

__device__ __forceinline__ void cpa16(u32 dst, const void* src) {
    asm volatile("cp.async.cg.shared.global [%0], [%1], 16;" :: "r"(dst), "l"(src));
}
__device__ __forceinline__ u32 split_pack(float v0, float v1, float* r0, float* r1) {
    __half h0 = __float2half(v0), h1 = __float2half(v1);
    *r0 = v0 - __half2float(h0);
    *r1 = v1 - __half2float(h1);
    return (u32)__half_as_ushort(h0) | ((u32)__half_as_ushort(h1) << 16);
}
__device__ __forceinline__ u32 pack_only(float v0, float v1) {
    __half h0 = __float2half(v0), h1 = __float2half(v1);
    return (u32)__half_as_ushort(h0) | ((u32)__half_as_ushort(h1) << 16);
}

// ---------------------------------------------------------------------------
// Kernel 0: per-code squared norms (+ zero rescan counter)
// ---------------------------------------------------------------------------
__global__ void csq_kernel(const float* __restrict__ cb) {
    if (blockIdx.x == 0 && threadIdx.x == 0) g_rcount = 0;
    int w = threadIdx.x >> 5, lane = threadIdx.x & 31;
    int row = blockIdx.x * 8 + w;
    const float* r = cb + (size_t)row * CC;
    float s = 0.f;
#pragma unroll
    for (int j = 0; j < 8; j++) { float v = r[lane + j*32]; s = fmaf(v, v, s); }
#pragma unroll
    for (int off = 16; off; off >>= 1) s += __shfl_xor_sync(0xffffffffu, s, off);
    if (lane == 0) g_csq[row] = s;
}

// ---------------------------------------------------------------------------
// Prep: x -> fp16 hi/lo A-fragment slabs, via coalesced smem tile.
//   Block = one (mtile, g): loads x[32 k][128 m] coalesced, emits fragments.
//   A frag (m16n8k16): reg e = (r = lane/4+(e&1)*8, k = (lane%4)*2+((e>>1)&1)*8)
// ---------------------------------------------------------------------------
#define XS_LD 132
__global__ void prep_x(const float* __restrict__ x) {
    __shared__ float xs[32 * XS_LD];
    const int tid = threadIdx.x;
    const int mtile = blockIdx.x >> 3, g = blockIdx.x & 7;
    const int q0 = mtile * 128;
    const int b = q0 >> 11, l0 = q0 & 2047;
    const float* src = x + ((size_t)b * CC + g * 32) * LL + l0;

    // Coalesced load: 32 rows x 128 floats (float4, lanes->consecutive l)
#pragma unroll
    for (int j = 0; j < 4; j++) {
        int i  = tid + j * 256;          // 1024 float4
        int c  = i >> 5, l4 = i & 31;
        float4 v = *(const float4*)(src + (size_t)c * LL + l4 * 4);
        *(float4*)(xs + c * XS_LD + l4 * 4) = v;
    }
    __syncthreads();

    const int msub = tid >> 5, lane = tid & 31;
#pragma unroll
    for (int kc = 0; kc < 2; kc++) {
        u32 ph[4], pl[4];
#pragma unroll
        for (int e = 0; e < 4; e++) {
            int m  = msub * 16 + (lane >> 2) + (e & 1) * 8;
            int k  = kc * 16 + (lane & 3) * 2 + ((e >> 1) & 1) * 8;
            float v0 = xs[k * XS_LD + m];
            float v1 = xs[(k + 1) * XS_LD + m];
            float r0, r1;
            ph[e] = split_pack(v0, v1, &r0, &r1);
            pl[e] = pack_only(r0, r1);
        }
        size_t idx = ((size_t)(((mtile * 8 + g) * 2 + kc) * 8 + msub) * 32 + lane);
        ((uint4*)g_Ah)[idx] = make_uint4(ph[0], ph[1], ph[2], ph[3]);
        ((uint4*)g_Al)[idx] = make_uint4(pl[0], pl[1], pl[2], pl[3]);
    }
}

// ---------------------------------------------------------------------------
// Prep: codebook -> fp16 hi/lo B-fragment slabs, via coalesced smem tile.
//   Block = one (ntile, g): loads cb[128 n][32 k] coalesced, emits fragments.
//   B frag: reg e = (n = lane/4, k = (lane%4)*2 + e*8)
// ---------------------------------------------------------------------------
#define CS_LD 36
__global__ void prep_cb(const float* __restrict__ cb) {
    __shared__ float cs[128 * CS_LD];
    const int tid = threadIdx.x;
    const int ntile = blockIdx.x >> 3, g = blockIdx.x & 7;
    const int n0 = ntile * 128;
    const float* src = cb + (size_t)n0 * CC + g * 32;

#pragma unroll
    for (int j = 0; j < 4; j++) {
        int i  = tid + j * 256;          // 1024 float4
        int n  = i >> 3, k4 = i & 7;
        float4 v = *(const float4*)(src + (size_t)n * CC + k4 * 4);
        *(float4*)(cs + n * CS_LD + k4 * 4) = v;
    }
    __syncthreads();

    const int lane = tid & 31;
#pragma unroll
    for (int h = 0; h < 2; h++) {
        int nsub = (tid >> 5) + h * 8;
        int n = nsub * 8 + (lane >> 2);
#pragma unroll
        for (int kc = 0; kc < 2; kc++) {
            u32 ph[2], pl[2];
#pragma unroll
            for (int e = 0; e < 2; e++) {
                int k = kc * 16 + (lane & 3) * 2 + e * 8;
                float v0 = cs[n * CS_LD + k];
                float v1 = cs[n * CS_LD + k + 1];
                float r0, r1;
                ph[e] = split_pack(v0, v1, &r0, &r1);
                pl[e] = pack_only(r0, r1);
            }
            size_t idx = ((size_t)(((ntile * 8 + g) * 2 + kc) * 16 + nsub) * 32 + lane);
            ((uint2*)g_Bh)[idx] = make_uint2(ph[0], ph[1]);
            ((uint2*)g_Bl)[idx] = make_uint2(pl[0], pl[1]);
        }
    }
}

// ---------------------------------------------------------------------------
// GEMM: 3-term fp16 split mma, fused top-2 argmax. 3-stage cp.async pipeline,
// ONE __syncthreads per k-chunk. grid (128,64), 256 thr, warp tile 64x32.
// ---------------------------------------------------------------------------
__device__ __forceinline__ void stage_chunk(u32 sb, int buf, int bm, int bn,
                                            int g, int tid) {
    u32 d = sb + (u32)buf * STAGE_B;
    const char* ah = (const char*)g_Ah + (size_t)(bm * 8 + g) * SLAB_B;
    const char* al = (const char*)g_Al + (size_t)(bm * 8 + g) * SLAB_B;
    const char* bh = (const char*)g_Bh + (size_t)(bn * 8 + g) * SLAB_B;
    const char* bl = (const char*)g_Bl + (size_t)(bn * 8 + g) * SLAB_B;
#pragma unroll
    for (int j = 0; j < 2; j++) {
        int i = (tid + j * 256) * 16;
        cpa16(d +          i, ah + i);
        cpa16(d +  8192u + i, al + i);
        cpa16(d + 16384u + i, bh + i);
        cpa16(d + 24576u + i, bl + i);
    }
    asm volatile("cp.async.commit_group;" ::: "memory");
}

__global__ void __launch_bounds__(256) gemm_kernel() {
    extern __shared__ __align__(16) char smem[];
    float* sm = (float*)smem;
    const u32 sb = (u32)__cvta_generic_to_shared(smem);
    const int tid = threadIdx.x, lane = tid & 31, warp = tid >> 5;
    const int wm = warp & 1, wn = warp >> 1;       // 2 x 4 warp grid
    const int bm = blockIdx.x, bn = blockIdx.y;

    // Hoisted per-warp smem offsets
    const int aOff = (wm * 4 * 32 + lane) * 16;          // + kc*4096 + i*512
    const int bOff = 16384 + (wn * 4 * 32 + lane) * 8;   // + kc*4096 + i*256

    float acc[4][4][4];
#pragma unroll
    for (int i = 0; i < 4; i++)
#pragma unroll
        for (int j = 0; j < 4; j++)
#pragma unroll
            for (int e = 0; e < 4; e++) acc[i][j][e] = 0.f;

    stage_chunk(sb, 0, bm, bn, 0, tid);
    stage_chunk(sb, 1, bm, bn, 1, tid);

    int bufc = 0;                                  // g % 3
#pragma unroll 1
    for (int g = 0; g < NG; g++) {
        if (g < NG - 1) asm volatile("cp.async.wait_group 1;" ::: "memory");
        else            asm volatile("cp.async.wait_group 0;" ::: "memory");
        __syncthreads();
        if (g < NG - 2) {
            int nb = bufc + 2; if (nb >= NSTG) nb -= NSTG;
            stage_chunk(sb, nb, bm, bn, g + 2, tid);
        }
        const char* buf = smem + bufc * STAGE_B;
#pragma unroll
        for (int kc = 0; kc < 2; kc++) {
            uint4 ah[4], al[4]; uint2 bh[4], bl[4];
#pragma unroll
            for (int i = 0; i < 4; i++) {
                int mo = aOff + kc * 4096 + i * 512;
                ah[i] = *(const uint4*)(buf + mo);
                al[i] = *(const uint4*)(buf + 8192 + mo);
                int no = bOff + kc * 4096 + i * 256;
                bh[i] = *(const uint2*)(buf + no);
                bl[i] = *(const uint2*)(buf + 8192 + no);
            }
#pragma unroll
            for (int i = 0; i < 4; i++)
#pragma unroll
                for (int j = 0; j < 4; j++) {
                    MMA_F16(acc[i][j], ah[i], bh[j]);
                    MMA_F16(acc[i][j], ah[i], bl[j]);
                    MMA_F16(acc[i][j], al[i], bh[j]);
                }
        }
        if (++bufc >= NSTG) bufc = 0;
    }

    // Epilogue: top-2 of score = csq[n] - 2*dot per m-row; first-index ties.
    float bv[4][2]; int bi[4][2]; float b2[4][2];
#pragma unroll
    for (int i = 0; i < 4; i++)
#pragma unroll
        for (int h = 0; h < 2; h++) {
            bv[i][h] = -3.0e38f; bi[i][h] = 0x7fffffff; b2[i][h] = -3.0e38f;
        }

#define UPD(i, h, s, n) do { \
    if ((s) > bv[i][h]) { b2[i][h] = bv[i][h]; bv[i][h] = (s); bi[i][h] = (n); } \
    else b2[i][h] = fmaxf(b2[i][h], (s)); } while (0)

#pragma unroll
    for (int j = 0; j < 4; j++) {                  // n ascending across j
        int n0 = bn * 128 + wn * 32 + j * 8 + (lane & 3) * 2;
        float cs0 = g_csq[n0], cs1 = g_csq[n0 + 1];
#pragma unroll
        for (int i = 0; i < 4; i++) {
            float s0 = fmaf(-2.f, acc[i][j][0], cs0);  UPD(i, 0, s0, n0);
            float s1 = fmaf(-2.f, acc[i][j][1], cs1);  UPD(i, 0, s1, n0 + 1);
            float s2 = fmaf(-2.f, acc[i][j][2], cs0);  UPD(i, 1, s2, n0);
            float s3 = fmaf(-2.f, acc[i][j][3], cs1);  UPD(i, 1, s3, n0 + 1);
        }
    }
#pragma unroll
    for (int off = 1; off <= 2; off <<= 1)
#pragma unroll
        for (int i = 0; i < 4; i++)
#pragma unroll
            for (int h = 0; h < 2; h++) {
                float ov  = __shfl_xor_sync(0xffffffffu, bv[i][h], off);
                int   oi  = __shfl_xor_sync(0xffffffffu, bi[i][h], off);
                float ov2 = __shfl_xor_sync(0xffffffffu, b2[i][h], off);
                if (ov > bv[i][h] || (ov == bv[i][h] && oi < bi[i][h])) {
                    b2[i][h] = fmaxf(bv[i][h], ov2);
                    bv[i][h] = ov; bi[i][h] = oi;
                } else {
                    b2[i][h] = fmaxf(b2[i][h], ov);
                }
            }
    // smem reduce across the 4 n-warp-columns (buffer 0 region free: last
    // compute chunk g=7 used buffer 1, and all warps passed the g=7 barrier)
    float* rv  = sm;                   // [4][128]
    int*   ri  = (int*)(sm + 512);     // [4][128]
    float* rv2 = sm + 1024;            // [4][128]
    if ((lane & 3) == 0) {
        int r = lane >> 2;
#pragma unroll
        for (int i = 0; i < 4; i++)
#pragma unroll
            for (int h = 0; h < 2; h++) {
                int ml = wm * 64 + i * 16 + h * 8 + r;
                rv [wn * 128 + ml] = bv[i][h];
                ri [wn * 128 + ml] = bi[i][h];
                rv2[wn * 128 + ml] = b2[i][h];
            }
    }
    __syncthreads();
    if (tid < 128) {
        float v = rv[tid]; int ix = ri[tid]; float v2 = rv2[tid];
#pragma unroll
        for (int w = 1; w < 4; w++) {              // wn ascending = n ascending
            float ov = rv[w * 128 + tid]; int oi = ri[w * 128 + tid];
            float ov2 = rv2[w * 128 + tid];
            if (ov > v || (ov == v && oi < ix)) { v2 = fmaxf(v, ov2); v = ov; ix = oi; }
            else v2 = fmaxf(v2, ov);
        }
        int q = bm * 128 + tid;
        g_pval[bn][q] = v;
        g_pidx[bn][q] = ix;
        g_pv2 [bn][q] = v2;
    }
}

// ---------------------------------------------------------------------------
// Combine partials -> code; flag small-gap queries for exact rescan
// ---------------------------------------------------------------------------
__global__ void combine_kernel() {
    int q = blockIdx.x * 256 + threadIdx.x;
    float v = g_pval[0][q]; int ix = g_pidx[0][q]; float v2 = g_pv2[0][q];
#pragma unroll 8
    for (int s = 1; s < NNT; s++) {                // ascending n blocks
        float ov = g_pval[s][q]; int oi = g_pidx[s][q]; float ov2 = g_pv2[s][q];
        if (ov > v || (ov == v && oi < ix)) { v2 = fmaxf(v, ov2); v = ov; ix = oi; }
        else v2 = fmaxf(v2, ov);
    }
    g_code[q] = ix;
    if (v - v2 < EPS_GAP) {
        int slot = atomicAdd(&g_rcount, 1);
        g_rlist[slot] = q;
    }
}

// ---------------------------------------------------------------------------
// Exact rescan (bit-identical to the verified round-2 scalar argmax)
// ---------------------------------------------------------------------------
__global__ void rescan_kernel(const float* __restrict__ x,
                              const float* __restrict__ cb) {
    __shared__ float xq[CC];
    __shared__ float sv[256];
    __shared__ int   si[256];
    const int tid = threadIdx.x;
    const int count = g_rcount;

    for (int it = blockIdx.x; it < count; it += gridDim.x) {
        const int q = g_rlist[it];
        const int b = q >> 11, l = q & 2047;
        xq[tid] = x[((size_t)(b * CC + tid)) * LL + l];
        __syncthreads();

        float bv = -3.0e38f; int bi = 0x7fffffff;
#pragma unroll 4
        for (int jj = 0; jj < 32; jj++) {
            int n = tid * 32 + jj;
            const float* row = cb + (size_t)n * CC;
            float acc = 0.f;
#pragma unroll
            for (int c4 = 0; c4 < CC / 4; c4++) {
                float4 v = *(const float4*)(row + c4 * 4);
                acc = fmaf(xq[c4 * 4 + 0], v.x, acc);
                acc = fmaf(xq[c4 * 4 + 1], v.y, acc);
                acc = fmaf(xq[c4 * 4 + 2], v.z, acc);
                acc = fmaf(xq[c4 * 4 + 3], v.w, acc);
            }
            float s = fmaf(-2.f, acc, g_csq[n]);
            if (s > bv) { bv = s; bi = n; }
        }
        sv[tid] = bv; si[tid] = bi;
        __syncthreads();
        for (int off = 128; off; off >>= 1) {
            if (tid < off) {
                float ov = sv[tid + off]; int oi = si[tid + off];
                if (ov > sv[tid] || (ov == sv[tid] && oi < si[tid])) {
                    sv[tid] = ov; si[tid] = oi;
                }
            }
            __syncthreads();
        }
        if (tid == 0) g_code[q] = si[0];
        __syncthreads();
    }
}

// ---------------------------------------------------------------------------
// Gather emb (B,C,L) — fully coalesced: block = 32 consecutive l; the 32
// needed codebook rows are staged into smem with coalesced float4 loads.
// ---------------------------------------------------------------------------
__global__ void gather_kernel(const float* __restrict__ x,
                              const float* __restrict__ cb,
                              float* __restrict__ out) {
    __shared__ float rows[32][CC + 1];     // +1 pad: row-major reads conflict-free
    __shared__ float ws[8];
    const int tid = threadIdx.x, lane = tid & 31, w = tid >> 5;
    const int q0 = blockIdx.x * 32;

    if (tid < 32) out[q0 + tid] = (float)g_code[q0 + tid];

    // Stage 32 codebook rows (warp w loads rows 4w..4w+3, coalesced)
#pragma unroll
    for (int rr = 0; rr < 4; rr++) {
        int r = w * 4 + rr;
        const float4* src = (const float4*)(cb + (size_t)g_code[q0 + r] * CC);
#pragma unroll
        for (int j = 0; j < 2; j++) {
            int i = lane + j * 32;         // 64 float4 per row
            float4 v = src[i];
            rows[r][i * 4 + 0] = v.x; rows[r][i * 4 + 1] = v.y;
            rows[r][i * 4 + 2] = v.z; rows[r][i * 4 + 3] = v.w;
        }
    }
    __syncthreads();

    const int q = q0 + lane;
    const int b = q >> 11, l = q & 2047;
    float* emb = out + NQ;
    float lsum = 0.f;
#pragma unroll
    for (int j = 0; j < 32; j++) {
        int c = w * 32 + j;
        float e = rows[lane][c];
        size_t pos = ((size_t)(b * CC + c)) * LL + l;   // lanes -> consecutive l
        emb[pos] = e;
        float d = x[pos] - e;
        lsum = fmaf(d, d, lsum);
    }
#pragma unroll
    for (int off = 16; off; off >>= 1)
        lsum += __shfl_xor_sync(0xffffffffu, lsum, off);
    if (lane == 0) ws[w] = lsum;
    __syncthreads();
    if (tid == 0) {
        float s = 0.f;
#pragma unroll
        for (int i = 0; i < 8; i++) s += ws[i];
        g_losspart[blockIdx.x] = s;
    }
}

__global__ void loss_kernel(float* __restrict__ out) {
    __shared__ float s[256];
    float a = 0.f;
    for (int i = threadIdx.x; i < NQ / 32; i += 256) a += g_losspart[i];
    s[threadIdx.x] = a;
    __syncthreads();
    for (int off = 128; off; off >>= 1) {
        if (threadIdx.x < off) s[threadIdx.x] += s[threadIdx.x + off];
        __syncthreads();
    }
    if (threadIdx.x == 0) out[NQ + NEMB] = s[0] / (float)NEMB;
}

// ---------------------------------------------------------------------------
extern "C" void kernel_launch(void* const* d_in, const int* in_sizes, int n_in,
                              void* d_out, int out_size) {
    const float* x  = (const float*)d_in[0];
    const float* cb = (const float*)d_in[1];
    if (n_in >= 2 && in_sizes[0] == KK * CC && in_sizes[1] == BBATCH * CC * LL) {
        const float* t = x; x = cb; cb = t;
    }
    float* out = (float*)d_out;

    cudaFuncSetAttribute(gemm_kernel,
        cudaFuncAttributeMaxDynamicSharedMemorySize, NSTG * STAGE_B);

    csq_kernel <<<KK / 8, 256>>>(cb);
    prep_x     <<<NMT * NG, 256>>>(x);
    prep_cb    <<<NNT * NG, 256>>>(cb);
    gemm_kernel<<<dim3(NMT, NNT), 256, NSTG * STAGE_B>>>();
    combine_kernel<<<NQ / 256, 256>>>();
    rescan_kernel <<<256, 256>>>(x, cb);
    gather_kernel <<<NQ / 32, 256>>>(x, cb, out);
    loss_kernel   <<<1, 256>>>(out);
    (void)out_size;
}

// round 11
// speedup vs baseline: 3.3139x; 1.0955x over previous
#include <cuda_runtime.h>
#include <cuda_fp16.h>
#include <cstddef>

typedef unsigned int u32;

// Problem shape
#define BBATCH 8
#define CC   256
#define LL   2048
#define KK   8192
#define NQ   16384
#define NEMB (BBATCH*CC*LL)
#define NMT  128              // m-tiles of 128 queries
#define NNT  32               // n-tiles of 256 codes
#define NG   8                // k-chunks of 32 (staged)
#define EPS_GAP 0.06f

#define A_SLAB_B 8192         // per-(mtile,g) A fragment slab (hi or lo)
#define B_SLAB_B 16384        // per-(ntile256,g) B fragment slab (hi only)
#define STAGE_B 32768         // Ah 8K | Al 8K | Bh 16K
#define NSTG 3

// Static scratch (fragment-major fp16 slabs)
__device__ __align__(16) u32 g_Ah[NMT*NG*A_SLAB_B/4];   // 8MB
__device__ __align__(16) u32 g_Al[NMT*NG*A_SLAB_B/4];
__device__ __align__(16) u32 g_Bh[NNT*NG*B_SLAB_B/4];   // 4MB
__device__ float g_csq[KK];
__device__ float g_pval[NNT][NQ];
__device__ int   g_pidx[NNT][NQ];
__device__ float g_pv2[NNT][NQ];
__device__ int   g_code[NQ];
__device__ int   g_rlist[NQ];
__device__ int   g_rcount;
__device__ float g_losspart[NQ/32];

// m16n8k16 f16 mma, fp32 accumulate
#define MMA_F16(d, a, b) \
    asm volatile("mma.sync.aligned.m16n8k16.row.col.f32.f16.f16.f32 " \
        "{%0,%1,%2,%3},{%4,%5,%6,%7},{%8,%9},{%0,%1,%2,%3};" \
        : "+f"(d[0]), "+f"(d[1]), "+f"(d[2]), "+f"(d[3]) \
        : "r"((a).x), "r"((a).y), "r"((a).z), "r"((a).w), \
          "r"((b).x), "r"((b).y))

__device__ __forceinline__ void cpa16(u32 dst, const void* src) {
    asm volatile("cp.async.cg.shared.global [%0], [%1], 16;" :: "r"(dst), "l"(src));
}
__device__ __forceinline__ u32 split_pack(float v0, float v1, float* r0, float* r1) {
    __half h0 = __float2half(v0), h1 = __float2half(v1);
    *r0 = v0 - __half2float(h0);
    *r1 = v1 - __half2float(h1);
    return (u32)__half_as_ushort(h0) | ((u32)__half_as_ushort(h1) << 16);
}
__device__ __forceinline__ u32 pack_only(float v0, float v1) {
    __half h0 = __float2half(v0), h1 = __float2half(v1);
    return (u32)__half_as_ushort(h0) | ((u32)__half_as_ushort(h1) << 16);
}

// ---------------------------------------------------------------------------
// Kernel 0: per-code squared norms (+ zero rescan counter)
// ---------------------------------------------------------------------------
__global__ void csq_kernel(const float* __restrict__ cb) {
    if (blockIdx.x == 0 && threadIdx.x == 0) g_rcount = 0;
    int w = threadIdx.x >> 5, lane = threadIdx.x & 31;
    int row = blockIdx.x * 8 + w;
    const float* r = cb + (size_t)row * CC;
    float s = 0.f;
#pragma unroll
    for (int j = 0; j < 8; j++) { float v = r[lane + j*32]; s = fmaf(v, v, s); }
#pragma unroll
    for (int off = 16; off; off >>= 1) s += __shfl_xor_sync(0xffffffffu, s, off);
    if (lane == 0) g_csq[row] = s;
}

// ---------------------------------------------------------------------------
// Prep: x -> fp16 hi/lo A-fragment slabs via coalesced smem tile.
//   A frag (m16n8k16): reg e = (r = lane/4+(e&1)*8, k = (lane%4)*2+((e>>1)&1)*8)
// ---------------------------------------------------------------------------
#define XS_LD 132
__global__ void prep_x(const float* __restrict__ x) {
    __shared__ float xs[32 * XS_LD];
    const int tid = threadIdx.x;
    const int mtile = blockIdx.x >> 3, g = blockIdx.x & 7;
    const int q0 = mtile * 128;
    const int b = q0 >> 11, l0 = q0 & 2047;
    const float* src = x + ((size_t)b * CC + g * 32) * LL + l0;

#pragma unroll
    for (int j = 0; j < 4; j++) {
        int i  = tid + j * 256;          // 1024 float4
        int c  = i >> 5, l4 = i & 31;
        float4 v = *(const float4*)(src + (size_t)c * LL + l4 * 4);
        *(float4*)(xs + c * XS_LD + l4 * 4) = v;
    }
    __syncthreads();

    const int msub = tid >> 5, lane = tid & 31;
#pragma unroll
    for (int kc = 0; kc < 2; kc++) {
        u32 ph[4], pl[4];
#pragma unroll
        for (int e = 0; e < 4; e++) {
            int m  = msub * 16 + (lane >> 2) + (e & 1) * 8;
            int k  = kc * 16 + (lane & 3) * 2 + ((e >> 1) & 1) * 8;
            float v0 = xs[k * XS_LD + m];
            float v1 = xs[(k + 1) * XS_LD + m];
            float r0, r1;
            ph[e] = split_pack(v0, v1, &r0, &r1);
            pl[e] = pack_only(r0, r1);
        }
        size_t idx = ((size_t)(((mtile * 8 + g) * 2 + kc) * 8 + msub) * 32 + lane);
        ((uint4*)g_Ah)[idx] = make_uint4(ph[0], ph[1], ph[2], ph[3]);
        ((uint4*)g_Al)[idx] = make_uint4(pl[0], pl[1], pl[2], pl[3]);
    }
}

// ---------------------------------------------------------------------------
// Prep: codebook -> fp16 (hi only) B-fragment slabs via coalesced smem tile.
//   Block = one (ntile of 256 n, g). B frag: reg e = (n=lane/4, k=(lane%4)*2+e*8)
//   Slab layout: [kc2][nsub32][lane32][uint2] = 16KB
// ---------------------------------------------------------------------------
#define CS_LD 36
__global__ void prep_cb(const float* __restrict__ cb) {
    __shared__ float cs[256 * CS_LD];
    const int tid = threadIdx.x;
    const int ntile = blockIdx.x >> 3, g = blockIdx.x & 7;
    const int n0 = ntile * 256;
    const float* src = cb + (size_t)n0 * CC + g * 32;

#pragma unroll
    for (int j = 0; j < 8; j++) {
        int i  = tid + j * 256;          // 2048 float4
        int n  = i >> 3, k4 = i & 7;
        float4 v = *(const float4*)(src + (size_t)n * CC + k4 * 4);
        *(float4*)(cs + n * CS_LD + k4 * 4) = v;
    }
    __syncthreads();

    const int lane = tid & 31;
#pragma unroll
    for (int h = 0; h < 4; h++) {
        int nsub = (tid >> 5) + h * 8;       // 0..31
        int n = nsub * 8 + (lane >> 2);
#pragma unroll
        for (int kc = 0; kc < 2; kc++) {
            u32 ph[2];
#pragma unroll
            for (int e = 0; e < 2; e++) {
                int k = kc * 16 + (lane & 3) * 2 + e * 8;
                ph[e] = pack_only(cs[n * CS_LD + k], cs[n * CS_LD + k + 1]);
            }
            size_t idx = ((size_t)(((ntile * 8 + g) * 2 + kc) * 32 + nsub) * 32 + lane);
            ((uint2*)g_Bh)[idx] = make_uint2(ph[0], ph[1]);
        }
    }
}

// ---------------------------------------------------------------------------
// GEMM: 2-term fp16 split mma (ah*bh + al*bh), fused top-2 argmax.
//   grid (128, 32), 256 thr; block tile 128x256, warp tile 64x64 (2x4 warps).
//   Smem: 3 x 32KB stages [Ah 8K|Al 8K|Bh 16K], cp.async, 1 barrier/chunk.
// ---------------------------------------------------------------------------
__device__ __forceinline__ void stage_chunk(u32 sb, int buf, int bm, int bn,
                                            int g, int tid) {
    u32 d = sb + (u32)buf * STAGE_B;
    const char* ah = (const char*)g_Ah + (size_t)(bm * 8 + g) * A_SLAB_B;
    const char* al = (const char*)g_Al + (size_t)(bm * 8 + g) * A_SLAB_B;
    const char* bh = (const char*)g_Bh + (size_t)(bn * 8 + g) * B_SLAB_B;
#pragma unroll
    for (int j = 0; j < 2; j++) {         // A hi/lo: 512 x 16B EACH (8KB each)
        int i = (tid + j * 256) * 16;
        cpa16(d +         i, ah + i);
        cpa16(d + 8192u + i, al + i);
    }
#pragma unroll
    for (int j = 0; j < 4; j++) {         // B: 1024 x 16B (16KB)
        int i = (tid + j * 256) * 16;
        cpa16(d + 16384u + i, bh + i);
    }
    asm volatile("cp.async.commit_group;" ::: "memory");
}

__global__ void __launch_bounds__(256) gemm_kernel() {
    extern __shared__ __align__(16) char smem[];
    float* sm = (float*)smem;
    const u32 sb = (u32)__cvta_generic_to_shared(smem);
    const int tid = threadIdx.x, lane = tid & 31, warp = tid >> 5;
    const int wm = warp & 1, wn = warp >> 1;       // 2 x 4 warp grid
    const int bm = blockIdx.x, bn = blockIdx.y;

    const int aOff = (wm * 4 * 32 + lane) * 16;            // + kc*4096 + i*512
    const int bOff = 16384 + (wn * 8 * 32 + lane) * 8;     // + kc*8192 + j*256

    float acc[4][8][4];
#pragma unroll
    for (int i = 0; i < 4; i++)
#pragma unroll
        for (int j = 0; j < 8; j++)
#pragma unroll
            for (int e = 0; e < 4; e++) acc[i][j][e] = 0.f;

    stage_chunk(sb, 0, bm, bn, 0, tid);
    stage_chunk(sb, 1, bm, bn, 1, tid);

    int bufc = 0;
#pragma unroll 1
    for (int g = 0; g < NG; g++) {
        if (g < NG - 1) asm volatile("cp.async.wait_group 1;" ::: "memory");
        else            asm volatile("cp.async.wait_group 0;" ::: "memory");
        __syncthreads();
        if (g < NG - 2) {
            int nb = bufc + 2; if (nb >= NSTG) nb -= NSTG;
            stage_chunk(sb, nb, bm, bn, g + 2, tid);
        }
        const char* buf = smem + bufc * STAGE_B;
#pragma unroll
        for (int kc = 0; kc < 2; kc++) {
            uint4 ah[4], al[4]; uint2 bh[8];
#pragma unroll
            for (int i = 0; i < 4; i++) {
                int mo = aOff + kc * 4096 + i * 512;
                ah[i] = *(const uint4*)(buf + mo);
                al[i] = *(const uint4*)(buf + 8192 + mo);
            }
#pragma unroll
            for (int j = 0; j < 8; j++)
                bh[j] = *(const uint2*)(buf + bOff + kc * 8192 + j * 256);
#pragma unroll
            for (int i = 0; i < 4; i++)
#pragma unroll
                for (int j = 0; j < 8; j++) {
                    MMA_F16(acc[i][j], ah[i], bh[j]);
                    MMA_F16(acc[i][j], al[i], bh[j]);
                }
        }
        if (++bufc >= NSTG) bufc = 0;
    }

    // Epilogue: top-2 of score = csq[n] - 2*dot per m-row; first-index ties.
    float bv[4][2]; int bi[4][2]; float b2[4][2];
#pragma unroll
    for (int i = 0; i < 4; i++)
#pragma unroll
        for (int h = 0; h < 2; h++) {
            bv[i][h] = -3.0e38f; bi[i][h] = 0x7fffffff; b2[i][h] = -3.0e38f;
        }

#define UPD(i, h, s, n) do { \
    if ((s) > bv[i][h]) { b2[i][h] = bv[i][h]; bv[i][h] = (s); bi[i][h] = (n); } \
    else b2[i][h] = fmaxf(b2[i][h], (s)); } while (0)

#pragma unroll
    for (int j = 0; j < 8; j++) {                  // n ascending across j
        int n0 = bn * 256 + wn * 64 + j * 8 + (lane & 3) * 2;
        float cs0 = g_csq[n0], cs1 = g_csq[n0 + 1];
#pragma unroll
        for (int i = 0; i < 4; i++) {
            float s0 = fmaf(-2.f, acc[i][j][0], cs0);  UPD(i, 0, s0, n0);
            float s1 = fmaf(-2.f, acc[i][j][1], cs1);  UPD(i, 0, s1, n0 + 1);
            float s2 = fmaf(-2.f, acc[i][j][2], cs0);  UPD(i, 1, s2, n0);
            float s3 = fmaf(-2.f, acc[i][j][3], cs1);  UPD(i, 1, s3, n0 + 1);
        }
    }
#pragma unroll
    for (int off = 1; off <= 2; off <<= 1)
#pragma unroll
        for (int i = 0; i < 4; i++)
#pragma unroll
            for (int h = 0; h < 2; h++) {
                float ov  = __shfl_xor_sync(0xffffffffu, bv[i][h], off);
                int   oi  = __shfl_xor_sync(0xffffffffu, bi[i][h], off);
                float ov2 = __shfl_xor_sync(0xffffffffu, b2[i][h], off);
                if (ov > bv[i][h] || (ov == bv[i][h] && oi < bi[i][h])) {
                    b2[i][h] = fmaxf(bv[i][h], ov2);
                    bv[i][h] = ov; bi[i][h] = oi;
                } else {
                    b2[i][h] = fmaxf(b2[i][h], ov);
                }
            }
    // smem reduce across the 4 n-warp-columns (wn ascending = n ascending)
    float* rv  = sm;                   // [4][128]
    int*   ri  = (int*)(sm + 512);     // [4][128]
    float* rv2 = sm + 1024;            // [4][128]
    if ((lane & 3) == 0) {
        int r = lane >> 2;
#pragma unroll
        for (int i = 0; i < 4; i++)
#pragma unroll
            for (int h = 0; h < 2; h++) {
                int ml = wm * 64 + i * 16 + h * 8 + r;
                rv [wn * 128 + ml] = bv[i][h];
                ri [wn * 128 + ml] = bi[i][h];
                rv2[wn * 128 + ml] = b2[i][h];
            }
    }
    __syncthreads();
    if (tid < 128) {
        float v = rv[tid]; int ix = ri[tid]; float v2 = rv2[tid];
#pragma unroll
        for (int w = 1; w < 4; w++) {
            float ov = rv[w * 128 + tid]; int oi = ri[w * 128 + tid];
            float ov2 = rv2[w * 128 + tid];
            if (ov > v || (ov == v && oi < ix)) { v2 = fmaxf(v, ov2); v = ov; ix = oi; }
            else v2 = fmaxf(v2, ov);
        }
        int q = bm * 128 + tid;
        g_pval[bn][q] = v;
        g_pidx[bn][q] = ix;
        g_pv2 [bn][q] = v2;
    }
}

// ---------------------------------------------------------------------------
// Combine partials -> code; flag small-gap queries for exact rescan
// ---------------------------------------------------------------------------
__global__ void combine_kernel() {
    int q = blockIdx.x * 256 + threadIdx.x;
    float v = g_pval[0][q]; int ix = g_pidx[0][q]; float v2 = g_pv2[0][q];
#pragma unroll 8
    for (int s = 1; s < NNT; s++) {                // ascending n blocks
        float ov = g_pval[s][q]; int oi = g_pidx[s][q]; float ov2 = g_pv2[s][q];
        if (ov > v || (ov == v && oi < ix)) { v2 = fmaxf(v, ov2); v = ov; ix = oi; }
        else v2 = fmaxf(v2, ov);
    }
    g_code[q] = ix;
    if (v - v2 < EPS_GAP) {
        int slot = atomicAdd(&g_rcount, 1);
        g_rlist[slot] = q;
    }
}

// ---------------------------------------------------------------------------
// Exact rescan, 2 queries per block (shared codebook stream). Bit-identical
// scalar arithmetic to the round-2-verified kernel.
// ---------------------------------------------------------------------------
__global__ void rescan_kernel(const float* __restrict__ x,
                              const float* __restrict__ cb) {
    __shared__ float xq[2][CC];
    __shared__ float sv[2][256];
    __shared__ int   si[2][256];
    const int tid = threadIdx.x;
    const int count = g_rcount;

    for (int it = blockIdx.x * 2; it < count; it += gridDim.x * 2) {
        const int nq = (it + 1 < count) ? 2 : 1;
#pragma unroll
        for (int p = 0; p < 2; p++) {
            if (p < nq) {
                int q = g_rlist[it + p];
                xq[p][tid] = x[((size_t)((q >> 11) * CC + tid)) * LL + (q & 2047)];
            } else {
                xq[p][tid] = 0.f;
            }
        }
        __syncthreads();

        float bv0 = -3.0e38f, bv1 = -3.0e38f; int bi0 = 0x7fffffff, bi1 = 0x7fffffff;
#pragma unroll 2
        for (int jj = 0; jj < 32; jj++) {
            int n = tid * 32 + jj;
            const float* row = cb + (size_t)n * CC;
            float a0 = 0.f, a1 = 0.f;
#pragma unroll
            for (int c4 = 0; c4 < CC / 4; c4++) {
                float4 v = *(const float4*)(row + c4 * 4);
                a0 = fmaf(xq[0][c4*4+0], v.x, a0); a0 = fmaf(xq[0][c4*4+1], v.y, a0);
                a0 = fmaf(xq[0][c4*4+2], v.z, a0); a0 = fmaf(xq[0][c4*4+3], v.w, a0);
                a1 = fmaf(xq[1][c4*4+0], v.x, a1); a1 = fmaf(xq[1][c4*4+1], v.y, a1);
                a1 = fmaf(xq[1][c4*4+2], v.z, a1); a1 = fmaf(xq[1][c4*4+3], v.w, a1);
            }
            float s0 = fmaf(-2.f, a0, g_csq[n]);
            float s1 = fmaf(-2.f, a1, g_csq[n]);
            if (s0 > bv0) { bv0 = s0; bi0 = n; }
            if (s1 > bv1) { bv1 = s1; bi1 = n; }
        }
        sv[0][tid] = bv0; si[0][tid] = bi0;
        sv[1][tid] = bv1; si[1][tid] = bi1;
        __syncthreads();
        for (int off = 128; off; off >>= 1) {
            if (tid < off) {
#pragma unroll
                for (int p = 0; p < 2; p++) {
                    float ov = sv[p][tid + off]; int oi = si[p][tid + off];
                    if (ov > sv[p][tid] || (ov == sv[p][tid] && oi < si[p][tid])) {
                        sv[p][tid] = ov; si[p][tid] = oi;
                    }
                }
            }
            __syncthreads();
        }
        if (tid < nq) g_code[g_rlist[it + tid]] = si[tid][0];
        __syncthreads();
    }
}

// ---------------------------------------------------------------------------
// Gather emb (B,C,L) — fully coalesced; codebook rows staged via smem.
// ---------------------------------------------------------------------------
__global__ void gather_kernel(const float* __restrict__ x,
                              const float* __restrict__ cb,
                              float* __restrict__ out) {
    __shared__ float rows[32][CC + 1];
    __shared__ float ws[8];
    const int tid = threadIdx.x, lane = tid & 31, w = tid >> 5;
    const int q0 = blockIdx.x * 32;

    if (tid < 32) out[q0 + tid] = (float)g_code[q0 + tid];

#pragma unroll
    for (int rr = 0; rr < 4; rr++) {
        int r = w * 4 + rr;
        const float4* src = (const float4*)(cb + (size_t)g_code[q0 + r] * CC);
#pragma unroll
        for (int j = 0; j < 2; j++) {
            int i = lane + j * 32;
            float4 v = src[i];
            rows[r][i * 4 + 0] = v.x; rows[r][i * 4 + 1] = v.y;
            rows[r][i * 4 + 2] = v.z; rows[r][i * 4 + 3] = v.w;
        }
    }
    __syncthreads();

    const int q = q0 + lane;
    const int b = q >> 11, l = q & 2047;
    float* emb = out + NQ;
    float lsum = 0.f;
#pragma unroll
    for (int j = 0; j < 32; j++) {
        int c = w * 32 + j;
        float e = rows[lane][c];
        size_t pos = ((size_t)(b * CC + c)) * LL + l;
        emb[pos] = e;
        float d = x[pos] - e;
        lsum = fmaf(d, d, lsum);
    }
#pragma unroll
    for (int off = 16; off; off >>= 1)
        lsum += __shfl_xor_sync(0xffffffffu, lsum, off);
    if (lane == 0) ws[w] = lsum;
    __syncthreads();
    if (tid == 0) {
        float s = 0.f;
#pragma unroll
        for (int i = 0; i < 8; i++) s += ws[i];
        g_losspart[blockIdx.x] = s;
    }
}

__global__ void loss_kernel(float* __restrict__ out) {
    __shared__ float s[256];
    float a = 0.f;
    for (int i = threadIdx.x; i < NQ / 32; i += 256) a += g_losspart[i];
    s[threadIdx.x] = a;
    __syncthreads();
    for (int off = 128; off; off >>= 1) {
        if (threadIdx.x < off) s[threadIdx.x] += s[threadIdx.x + off];
        __syncthreads();
    }
    if (threadIdx.x == 0) out[NQ + NEMB] = s[0] / (float)NEMB;
}

// ---------------------------------------------------------------------------
extern "C" void kernel_launch(void* const* d_in, const int* in_sizes, int n_in,
                              void* d_out, int out_size) {
    const float* x  = (const float*)d_in[0];
    const float* cb = (const float*)d_in[1];
    if (n_in >= 2 && in_sizes[0] == KK * CC && in_sizes[1] == BBATCH * CC * LL) {
        const float* t = x; x = cb; cb = t;
    }
    float* out = (float*)d_out;

    cudaFuncSetAttribute(gemm_kernel,
        cudaFuncAttributeMaxDynamicSharedMemorySize, NSTG * STAGE_B);

    csq_kernel <<<KK / 8, 256>>>(cb);
    prep_x     <<<NMT * NG, 256>>>(x);
    prep_cb    <<<NNT * NG, 256>>>(cb);
    gemm_kernel<<<dim3(NMT, NNT), 256, NSTG * STAGE_B>>>();
    combine_kernel<<<NQ / 256, 256>>>();
    rescan_kernel <<<128, 256>>>(x, cb);
    gather_kernel <<<NQ / 32, 256>>>(x, cb, out);
    loss_kernel   <<<1, 256>>>(out);
    (void)out_size;
}

// round 12
// speedup vs baseline: 3.3232x; 1.0028x over previous
#include <cuda_runtime.h>
#include <cuda_fp16.h>
#include <cstddef>

typedef unsigned int u32;

// Problem shape
#define BBATCH 8
#define CC   256
#define LL   2048
#define KK   8192
#define NQ   16384
#define NEMB (BBATCH*CC*LL)
#define NMT  128              // m-tiles of 128 queries
#define NNT  64               // n-tiles of 128 codes
#define NG   8                // k-chunks of 32 (staged)
#define EPS_GAP 0.06f

#define A_SLAB_B 8192         // per-(mtile,g) A fragment slab (hi or lo)
#define B_SLAB_B 8192         // per-(ntile128,g) B fragment slab (hi only)
#define STAGE_B 24576         // Ah 8K | Al 8K | Bh 8K
#define NSTG 3

// Static scratch (fragment-major fp16 slabs)
__device__ __align__(16) u32 g_Ah[NMT*NG*A_SLAB_B/4];   // 8MB
__device__ __align__(16) u32 g_Al[NMT*NG*A_SLAB_B/4];
__device__ __align__(16) u32 g_Bh[NNT*NG*B_SLAB_B/4];   // 4MB
__device__ float g_csq[KK];
__device__ float g_pval[NNT][NQ];
__device__ int   g_pidx[NNT][NQ];
__device__ float g_pv2[NNT][NQ];
__device__ int   g_code[NQ];
__device__ int   g_rlist[NQ];
__device__ int   g_rcount;
__device__ float g_losspart[NQ/32];

// m16n8k16 f16 mma, fp32 accumulate
#define MMA_F16(d, a, b) \
    asm volatile("mma.sync.aligned.m16n8k16.row.col.f32.f16.f16.f32 " \
        "{%0,%1,%2,%3},{%4,%5,%6,%7},{%8,%9},{%0,%1,%2,%3};" \
        : "+f"(d[0]), "+f"(d[1]), "+f"(d[2]), "+f"(d[3]) \
        : "r"((a).x), "r"((a).y), "r"((a).z), "r"((a).w), \
          "r"((b).x), "r"((b).y))

__device__ __forceinline__ void cpa16(u32 dst, const void* src) {
    asm volatile("cp.async.cg.shared.global [%0], [%1], 16;" :: "r"(dst), "l"(src));
}
__device__ __forceinline__ u32 split_pack(float v0, float v1, float* r0, float* r1) {
    __half h0 = __float2half(v0), h1 = __float2half(v1);
    *r0 = v0 - __half2float(h0);
    *r1 = v1 - __half2float(h1);
    return (u32)__half_as_ushort(h0) | ((u32)__half_as_ushort(h1) << 16);
}
__device__ __forceinline__ u32 pack_only(float v0, float v1) {
    __half h0 = __float2half(v0), h1 = __float2half(v1);
    return (u32)__half_as_ushort(h0) | ((u32)__half_as_ushort(h1) << 16);
}

// ---------------------------------------------------------------------------
// Kernel 0: per-code squared norms (+ zero rescan counter)
// ---------------------------------------------------------------------------
__global__ void csq_kernel(const float* __restrict__ cb) {
    if (blockIdx.x == 0 && threadIdx.x == 0) g_rcount = 0;
    int w = threadIdx.x >> 5, lane = threadIdx.x & 31;
    int row = blockIdx.x * 8 + w;
    const float* r = cb + (size_t)row * CC;
    float s = 0.f;
#pragma unroll
    for (int j = 0; j < 8; j++) { float v = r[lane + j*32]; s = fmaf(v, v, s); }
#pragma unroll
    for (int off = 16; off; off >>= 1) s += __shfl_xor_sync(0xffffffffu, s, off);
    if (lane == 0) g_csq[row] = s;
}

// ---------------------------------------------------------------------------
// Prep: x -> fp16 hi/lo A-fragment slabs via coalesced smem tile.
//   A frag (m16n8k16): reg e = (r = lane/4+(e&1)*8, k = (lane%4)*2+((e>>1)&1)*8)
// ---------------------------------------------------------------------------
#define XS_LD 132
__global__ void prep_x(const float* __restrict__ x) {
    __shared__ float xs[32 * XS_LD];
    const int tid = threadIdx.x;
    const int mtile = blockIdx.x >> 3, g = blockIdx.x & 7;
    const int q0 = mtile * 128;
    const int b = q0 >> 11, l0 = q0 & 2047;
    const float* src = x + ((size_t)b * CC + g * 32) * LL + l0;

#pragma unroll
    for (int j = 0; j < 4; j++) {
        int i  = tid + j * 256;          // 1024 float4
        int c  = i >> 5, l4 = i & 31;
        float4 v = *(const float4*)(src + (size_t)c * LL + l4 * 4);
        *(float4*)(xs + c * XS_LD + l4 * 4) = v;
    }
    __syncthreads();

    const int msub = tid >> 5, lane = tid & 31;
#pragma unroll
    for (int kc = 0; kc < 2; kc++) {
        u32 ph[4], pl[4];
#pragma unroll
        for (int e = 0; e < 4; e++) {
            int m  = msub * 16 + (lane >> 2) + (e & 1) * 8;
            int k  = kc * 16 + (lane & 3) * 2 + ((e >> 1) & 1) * 8;
            float v0 = xs[k * XS_LD + m];
            float v1 = xs[(k + 1) * XS_LD + m];
            float r0, r1;
            ph[e] = split_pack(v0, v1, &r0, &r1);
            pl[e] = pack_only(r0, r1);
        }
        size_t idx = ((size_t)(((mtile * 8 + g) * 2 + kc) * 8 + msub) * 32 + lane);
        ((uint4*)g_Ah)[idx] = make_uint4(ph[0], ph[1], ph[2], ph[3]);
        ((uint4*)g_Al)[idx] = make_uint4(pl[0], pl[1], pl[2], pl[3]);
    }
}

// ---------------------------------------------------------------------------
// Prep: codebook -> fp16 (hi only) B-fragment slabs via coalesced smem tile.
//   Block = one (ntile of 128 n, g). B frag: reg e = (n=lane/4, k=(lane%4)*2+e*8)
//   Slab layout: [kc2][nsub16][lane32][uint2] = 8KB
// ---------------------------------------------------------------------------
#define CS_LD 36
__global__ void prep_cb(const float* __restrict__ cb) {
    __shared__ float cs[128 * CS_LD];
    const int tid = threadIdx.x;
    const int ntile = blockIdx.x >> 3, g = blockIdx.x & 7;
    const int n0 = ntile * 128;
    const float* src = cb + (size_t)n0 * CC + g * 32;

#pragma unroll
    for (int j = 0; j < 4; j++) {
        int i  = tid + j * 256;          // 1024 float4
        int n  = i >> 3, k4 = i & 7;
        float4 v = *(const float4*)(src + (size_t)n * CC + k4 * 4);
        *(float4*)(cs + n * CS_LD + k4 * 4) = v;
    }
    __syncthreads();

    const int lane = tid & 31;
#pragma unroll
    for (int h = 0; h < 2; h++) {
        int nsub = (tid >> 5) + h * 8;       // 0..15
        int n = nsub * 8 + (lane >> 2);
#pragma unroll
        for (int kc = 0; kc < 2; kc++) {
            u32 ph[2];
#pragma unroll
            for (int e = 0; e < 2; e++) {
                int k = kc * 16 + (lane & 3) * 2 + e * 8;
                ph[e] = pack_only(cs[n * CS_LD + k], cs[n * CS_LD + k + 1]);
            }
            size_t idx = ((size_t)(((ntile * 8 + g) * 2 + kc) * 16 + nsub) * 32 + lane);
            ((uint2*)g_Bh)[idx] = make_uint2(ph[0], ph[1]);
        }
    }
}

// ---------------------------------------------------------------------------
// GEMM: 2-term fp16 split mma (ah*bh + al*bh), fused top-2 argmax.
//   grid (128, 64), 256 thr, 2 CTAs/SM; block tile 128x128,
//   warp tile 32x64 (4m x 2n warps).
//   Smem: 3 x 24KB stages [Ah 8K|Al 8K|Bh 8K], cp.async, 1 barrier/chunk.
// ---------------------------------------------------------------------------
__device__ __forceinline__ void stage_chunk(u32 sb, int buf, int bm, int bn,
                                            int g, int tid) {
    u32 d = sb + (u32)buf * STAGE_B;
    const char* ah = (const char*)g_Ah + (size_t)(bm * 8 + g) * A_SLAB_B;
    const char* al = (const char*)g_Al + (size_t)(bm * 8 + g) * A_SLAB_B;
    const char* bh = (const char*)g_Bh + (size_t)(bn * 8 + g) * B_SLAB_B;
#pragma unroll
    for (int j = 0; j < 2; j++) {         // 512 x 16B each of Ah/Al/Bh
        int i = (tid + j * 256) * 16;
        cpa16(d +          i, ah + i);
        cpa16(d +  8192u + i, al + i);
        cpa16(d + 16384u + i, bh + i);
    }
    asm volatile("cp.async.commit_group;" ::: "memory");
}

__global__ void __launch_bounds__(256, 2) gemm_kernel() {
    extern __shared__ __align__(16) char smem[];
    float* sm = (float*)smem;
    const u32 sb = (u32)__cvta_generic_to_shared(smem);
    const int tid = threadIdx.x, lane = tid & 31, warp = tid >> 5;
    const int wm = warp & 3, wn = warp >> 2;       // 4m x 2n warp grid
    const int bm = blockIdx.x, bn = blockIdx.y;

    const int aOff = (wm * 2 * 32 + lane) * 16;            // + kc*4096 + i*512
    const int bOff = 16384 + (wn * 8 * 32 + lane) * 8;     // + kc*4096 + j*256

    float acc[2][8][4];
#pragma unroll
    for (int i = 0; i < 2; i++)
#pragma unroll
        for (int j = 0; j < 8; j++)
#pragma unroll
            for (int e = 0; e < 4; e++) acc[i][j][e] = 0.f;

    stage_chunk(sb, 0, bm, bn, 0, tid);
    stage_chunk(sb, 1, bm, bn, 1, tid);

    int bufc = 0;
#pragma unroll 1
    for (int g = 0; g < NG; g++) {
        if (g < NG - 1) asm volatile("cp.async.wait_group 1;" ::: "memory");
        else            asm volatile("cp.async.wait_group 0;" ::: "memory");
        __syncthreads();
        if (g < NG - 2) {
            int nb = bufc + 2; if (nb >= NSTG) nb -= NSTG;
            stage_chunk(sb, nb, bm, bn, g + 2, tid);
        }
        const char* buf = smem + bufc * STAGE_B;
#pragma unroll
        for (int kc = 0; kc < 2; kc++) {
            uint4 ah[2], al[2]; uint2 bh[8];
#pragma unroll
            for (int i = 0; i < 2; i++) {
                int mo = aOff + kc * 4096 + i * 512;
                ah[i] = *(const uint4*)(buf + mo);
                al[i] = *(const uint4*)(buf + 8192 + mo);
            }
#pragma unroll
            for (int j = 0; j < 8; j++)
                bh[j] = *(const uint2*)(buf + bOff + kc * 4096 + j * 256);
#pragma unroll
            for (int i = 0; i < 2; i++)
#pragma unroll
                for (int j = 0; j < 8; j++) {
                    MMA_F16(acc[i][j], ah[i], bh[j]);
                    MMA_F16(acc[i][j], al[i], bh[j]);
                }
        }
        if (++bufc >= NSTG) bufc = 0;
    }

    // Epilogue: top-2 of score = csq[n] - 2*dot per m-row; first-index ties.
    float bv[2][2]; int bi[2][2]; float b2[2][2];
#pragma unroll
    for (int i = 0; i < 2; i++)
#pragma unroll
        for (int h = 0; h < 2; h++) {
            bv[i][h] = -3.0e38f; bi[i][h] = 0x7fffffff; b2[i][h] = -3.0e38f;
        }

#define UPD(i, h, s, n) do { \
    if ((s) > bv[i][h]) { b2[i][h] = bv[i][h]; bv[i][h] = (s); bi[i][h] = (n); } \
    else b2[i][h] = fmaxf(b2[i][h], (s)); } while (0)

#pragma unroll
    for (int j = 0; j < 8; j++) {                  // n ascending across j
        int n0 = bn * 128 + wn * 64 + j * 8 + (lane & 3) * 2;
        float cs0 = g_csq[n0], cs1 = g_csq[n0 + 1];
#pragma unroll
        for (int i = 0; i < 2; i++) {
            float s0 = fmaf(-2.f, acc[i][j][0], cs0);  UPD(i, 0, s0, n0);
            float s1 = fmaf(-2.f, acc[i][j][1], cs1);  UPD(i, 0, s1, n0 + 1);
            float s2 = fmaf(-2.f, acc[i][j][2], cs0);  UPD(i, 1, s2, n0);
            float s3 = fmaf(-2.f, acc[i][j][3], cs1);  UPD(i, 1, s3, n0 + 1);
        }
    }
#pragma unroll
    for (int off = 1; off <= 2; off <<= 1)
#pragma unroll
        for (int i = 0; i < 2; i++)
#pragma unroll
            for (int h = 0; h < 2; h++) {
                float ov  = __shfl_xor_sync(0xffffffffu, bv[i][h], off);
                int   oi  = __shfl_xor_sync(0xffffffffu, bi[i][h], off);
                float ov2 = __shfl_xor_sync(0xffffffffu, b2[i][h], off);
                if (ov > bv[i][h] || (ov == bv[i][h] && oi < bi[i][h])) {
                    b2[i][h] = fmaxf(bv[i][h], ov2);
                    bv[i][h] = ov; bi[i][h] = oi;
                } else {
                    b2[i][h] = fmaxf(b2[i][h], ov);
                }
            }
    // smem reduce across the 2 n-warp-columns (wn ascending = n ascending)
    float* rv  = sm;                   // [2][128]
    int*   ri  = (int*)(sm + 256);     // [2][128]
    float* rv2 = sm + 512;             // [2][128]
    if ((lane & 3) == 0) {
        int r = lane >> 2;
#pragma unroll
        for (int i = 0; i < 2; i++)
#pragma unroll
            for (int h = 0; h < 2; h++) {
                int ml = wm * 32 + i * 16 + h * 8 + r;
                rv [wn * 128 + ml] = bv[i][h];
                ri [wn * 128 + ml] = bi[i][h];
                rv2[wn * 128 + ml] = b2[i][h];
            }
    }
    __syncthreads();
    if (tid < 128) {
        float v = rv[tid]; int ix = ri[tid]; float v2 = rv2[tid];
        {
            float ov = rv[128 + tid]; int oi = ri[128 + tid];
            float ov2 = rv2[128 + tid];
            if (ov > v || (ov == v && oi < ix)) { v2 = fmaxf(v, ov2); v = ov; ix = oi; }
            else v2 = fmaxf(v2, ov);
        }
        int q = bm * 128 + tid;
        g_pval[bn][q] = v;
        g_pidx[bn][q] = ix;
        g_pv2 [bn][q] = v2;
    }
}

// ---------------------------------------------------------------------------
// Combine partials -> code; flag small-gap queries for exact rescan
// ---------------------------------------------------------------------------
__global__ void combine_kernel() {
    int q = blockIdx.x * 256 + threadIdx.x;
    float v = g_pval[0][q]; int ix = g_pidx[0][q]; float v2 = g_pv2[0][q];
#pragma unroll 8
    for (int s = 1; s < NNT; s++) {                // ascending n blocks
        float ov = g_pval[s][q]; int oi = g_pidx[s][q]; float ov2 = g_pv2[s][q];
        if (ov > v || (ov == v && oi < ix)) { v2 = fmaxf(v, ov2); v = ov; ix = oi; }
        else v2 = fmaxf(v2, ov);
    }
    g_code[q] = ix;
    if (v - v2 < EPS_GAP) {
        int slot = atomicAdd(&g_rcount, 1);
        g_rlist[slot] = q;
    }
}

// ---------------------------------------------------------------------------
// Exact rescan, 2 queries per block (shared codebook stream). Bit-identical
// scalar arithmetic to the round-2-verified kernel.
// ---------------------------------------------------------------------------
__global__ void rescan_kernel(const float* __restrict__ x,
                              const float* __restrict__ cb) {
    __shared__ float xq[2][CC];
    __shared__ float sv[2][256];
    __shared__ int   si[2][256];
    const int tid = threadIdx.x;
    const int count = g_rcount;

    for (int it = blockIdx.x * 2; it < count; it += gridDim.x * 2) {
        const int nq = (it + 1 < count) ? 2 : 1;
#pragma unroll
        for (int p = 0; p < 2; p++) {
            if (p < nq) {
                int q = g_rlist[it + p];
                xq[p][tid] = x[((size_t)((q >> 11) * CC + tid)) * LL + (q & 2047)];
            } else {
                xq[p][tid] = 0.f;
            }
        }
        __syncthreads();

        float bv0 = -3.0e38f, bv1 = -3.0e38f; int bi0 = 0x7fffffff, bi1 = 0x7fffffff;
#pragma unroll 2
        for (int jj = 0; jj < 32; jj++) {
            int n = tid * 32 + jj;
            const float* row = cb + (size_t)n * CC;
            float a0 = 0.f, a1 = 0.f;
#pragma unroll
            for (int c4 = 0; c4 < CC / 4; c4++) {
                float4 v = *(const float4*)(row + c4 * 4);
                a0 = fmaf(xq[0][c4*4+0], v.x, a0); a0 = fmaf(xq[0][c4*4+1], v.y, a0);
                a0 = fmaf(xq[0][c4*4+2], v.z, a0); a0 = fmaf(xq[0][c4*4+3], v.w, a0);
                a1 = fmaf(xq[1][c4*4+0], v.x, a1); a1 = fmaf(xq[1][c4*4+1], v.y, a1);
                a1 = fmaf(xq[1][c4*4+2], v.z, a1); a1 = fmaf(xq[1][c4*4+3], v.w, a1);
            }
            float s0 = fmaf(-2.f, a0, g_csq[n]);
            float s1 = fmaf(-2.f, a1, g_csq[n]);
            if (s0 > bv0) { bv0 = s0; bi0 = n; }
            if (s1 > bv1) { bv1 = s1; bi1 = n; }
        }
        sv[0][tid] = bv0; si[0][tid] = bi0;
        sv[1][tid] = bv1; si[1][tid] = bi1;
        __syncthreads();
        for (int off = 128; off; off >>= 1) {
            if (tid < off) {
#pragma unroll
                for (int p = 0; p < 2; p++) {
                    float ov = sv[p][tid + off]; int oi = si[p][tid + off];
                    if (ov > sv[p][tid] || (ov == sv[p][tid] && oi < si[p][tid])) {
                        sv[p][tid] = ov; si[p][tid] = oi;
                    }
                }
            }
            __syncthreads();
        }
        if (tid < nq) g_code[g_rlist[it + tid]] = si[tid][0];
        __syncthreads();
    }
}

// ---------------------------------------------------------------------------
// Gather emb (B,C,L) — fully coalesced; codebook rows staged via smem.
// ---------------------------------------------------------------------------
__global__ void gather_kernel(const float* __restrict__ x,
                              const float* __restrict__ cb,
                              float* __restrict__ out) {
    __shared__ float rows[32][CC + 1];
    __shared__ float ws[8];
    const int tid = threadIdx.x, lane = tid & 31, w = tid >> 5;
    const int q0 = blockIdx.x * 32;

    if (tid < 32) out[q0 + tid] = (float)g_code[q0 + tid];

#pragma unroll
    for (int rr = 0; rr < 4; rr++) {
        int r = w * 4 + rr;
        const float4* src = (const float4*)(cb + (size_t)g_code[q0 + r] * CC);
#pragma unroll
        for (int j = 0; j < 2; j++) {
            int i = lane + j * 32;
            float4 v = src[i];
            rows[r][i * 4 + 0] = v.x; rows[r][i * 4 + 1] = v.y;
            rows[r][i * 4 + 2] = v.z; rows[r][i * 4 + 3] = v.w;
        }
    }
    __syncthreads();

    const int q = q0 + lane;
    const int b = q >> 11, l = q & 2047;
    float* emb = out + NQ;
    float lsum = 0.f;
#pragma unroll
    for (int j = 0; j < 32; j++) {
        int c = w * 32 + j;
        float e = rows[lane][c];
        size_t pos = ((size_t)(b * CC + c)) * LL + l;
        emb[pos] = e;
        float d = x[pos] - e;
        lsum = fmaf(d, d, lsum);
    }
#pragma unroll
    for (int off = 16; off; off >>= 1)
        lsum += __shfl_xor_sync(0xffffffffu, lsum, off);
    if (lane == 0) ws[w] = lsum;
    __syncthreads();
    if (tid == 0) {
        float s = 0.f;
#pragma unroll
        for (int i = 0; i < 8; i++) s += ws[i];
        g_losspart[blockIdx.x] = s;
    }
}

__global__ void loss_kernel(float* __restrict__ out) {
    __shared__ float s[256];
    float a = 0.f;
    for (int i = threadIdx.x; i < NQ / 32; i += 256) a += g_losspart[i];
    s[threadIdx.x] = a;
    __syncthreads();
    for (int off = 128; off; off >>= 1) {
        if (threadIdx.x < off) s[threadIdx.x] += s[threadIdx.x + off];
        __syncthreads();
    }
    if (threadIdx.x == 0) out[NQ + NEMB] = s[0] / (float)NEMB;
}

// ---------------------------------------------------------------------------
extern "C" void kernel_launch(void* const* d_in, const int* in_sizes, int n_in,
                              void* d_out, int out_size) {
    const float* x  = (const float*)d_in[0];
    const float* cb = (const float*)d_in[1];
    if (n_in >= 2 && in_sizes[0] == KK * CC && in_sizes[1] == BBATCH * CC * LL) {
        const float* t = x; x = cb; cb = t;
    }
    float* out = (float*)d_out;

    cudaFuncSetAttribute(gemm_kernel,
        cudaFuncAttributeMaxDynamicSharedMemorySize, NSTG * STAGE_B);

    csq_kernel <<<KK / 8, 256>>>(cb);
    prep_x     <<<NMT * NG, 256>>>(x);
    prep_cb    <<<NNT * NG, 256>>>(cb);
    gemm_kernel<<<dim3(NMT, NNT), 256, NSTG * STAGE_B>>>();
    combine_kernel<<<NQ / 256, 256>>>();
    rescan_kernel <<<256, 256>>>(x, cb);
    gather_kernel <<<NQ / 32, 256>>>(x, cb, out);
    loss_kernel   <<<1, 256>>>(out);
    (void)out_size;
}